// round 2
// baseline (speedup 1.0000x reference)
#include <cuda_runtime.h>
#include <cstdint>

#define T_SEQ 512
#define B_SZ  128
#define HID   128
#define DEMB  300
#define KPAD  304
#define MTOT  65536   // B*T

// ---------------- scratch (device globals; zero-init BSS) ----------------
__device__ float g_X0[MTOT * KPAD];        // padded embedded input (cols 300..303 stay 0)
__device__ float g_Wpad[1024 * KPAD];      // concat(w_ih_l0f, w_ih_l0r), K padded
__device__ float g_bias0[1024];
__device__ float g_bias1f[512];
__device__ float g_bias1r[512];
__device__ float g_xg0[MTOT * 1024];       // layer0 input gates, both dirs
__device__ float g_hs0[MTOT * 256];        // layer0 output [b][t][fwd128|rev128]
__device__ float g_xg1f[MTOT * 512];
__device__ float g_xg1r[128 * 512];
__device__ float g_h1last[128 * 256];      // [fwd h_T-1 | rev h_at_T-1]

// ---------------- helpers ----------------
__device__ __forceinline__ float sigf(float x) {
    return __fdividef(1.f, 1.f + __expf(-x));
}
__device__ __forceinline__ float tanh_fast(float x) {
    // 1 - 2/(e^{2x}+1): no NaN at +/-inf, abs err ~1e-7
    return 1.f - __fdividef(2.f, __expf(2.f * x) + 1.f);
}
__device__ __forceinline__ uint32_t smem_u32(const void* p) {
    uint32_t a;
    asm("{ .reg .u64 t; cvta.to.shared.u64 t, %1; cvt.u32.u64 %0, t; }" : "=r"(a) : "l"(p));
    return a;
}
__device__ __forceinline__ uint32_t mapa_sh(uint32_t a, uint32_t rank) {
    uint32_t o;
    asm("mapa.shared::cluster.u32 %0, %1, %2;" : "=r"(o) : "r"(a), "r"(rank));
    return o;
}
__device__ __forceinline__ float ld_cluster(uint32_t a) {
    float v;
    asm volatile("ld.shared::cluster.f32 %0, [%1];" : "=f"(v) : "r"(a));
    return v;
}
__device__ __forceinline__ uint32_t ctarank() {
    uint32_t r;
    asm("mov.u32 %0, %%cluster_ctarank;" : "=r"(r));
    return r;
}
#define CLUSTER_SYNC() do { \
    asm volatile("barrier.cluster.arrive.aligned;" ::: "memory"); \
    asm volatile("barrier.cluster.wait.aligned;" ::: "memory");   \
} while (0)

// ---------------- prep: pad weights, combine biases ----------------
__global__ void prep_kernel(const float* __restrict__ wf, const float* __restrict__ wr,
                            const float* __restrict__ bif, const float* __restrict__ bhf,
                            const float* __restrict__ bir, const float* __restrict__ bhr,
                            const float* __restrict__ b1if, const float* __restrict__ b1hf,
                            const float* __restrict__ b1ir, const float* __restrict__ b1hr) {
    int idx = blockIdx.x * blockDim.x + threadIdx.x;
    int stride = gridDim.x * blockDim.x;
    for (int i = idx; i < 1024 * KPAD; i += stride) {
        int n = i / KPAD, k = i - n * KPAD;
        float v = 0.f;
        if (k < DEMB) v = (n < 512) ? wf[n * DEMB + k] : wr[(n - 512) * DEMB + k];
        g_Wpad[i] = v;
    }
    if (idx < 1024)
        g_bias0[idx] = (idx < 512) ? (bif[idx] + bhf[idx]) : (bir[idx - 512] + bhr[idx - 512]);
    if (idx < 512) {
        g_bias1f[idx] = b1if[idx] + b1hf[idx];
        g_bias1r[idx] = b1ir[idx] + b1hr[idx];
    }
}

// ---------------- embedding gather ----------------
__global__ void embed_kernel(const int* __restrict__ x, const float* __restrict__ emb) {
    int idx = blockIdx.x * blockDim.x + threadIdx.x;
    int stride = gridDim.x * blockDim.x;
    const int total = MTOT * 75;  // 75 float4 per row (300 floats)
    for (int i = idx; i < total; i += stride) {
        int m = i / 75, q = i - m * 75;
        int v = x[m];
        float4 val = *(const float4*)(emb + (long)v * DEMB + q * 4);
        *(float4*)(g_X0 + (long)m * KPAD + q * 4) = val;
    }
}

// ---------------- fp32 tiled GEMM: C[m][n] = sum_k A[m][k]*B[n][k] + bias[n] ----------------
// BM=128, BN=64, BK=16, 256 threads, 8x4 per-thread tile. M%128==0, N%64==0, K%16==0.
__global__ __launch_bounds__(256) void gemm_bias_kernel(
    const float* __restrict__ A, int lda,
    const float* __restrict__ B, int ldb,
    float* __restrict__ C, int ldc,
    int K, const float* __restrict__ bias) {
    __shared__ float As[16][132];
    __shared__ float Bs[16][68];

    const int tid = threadIdx.x;
    const int bm = blockIdx.y * 128, bn = blockIdx.x * 64;
    const int tx = tid & 15, ty = tid >> 4;
    const int arow = tid >> 2, acol = tid & 3;

    float acc[8][4];
#pragma unroll
    for (int i = 0; i < 8; i++)
#pragma unroll
        for (int j = 0; j < 4; j++) acc[i][j] = 0.f;

    const float* Aptr = A + (long)(bm + arow) * lda + acol * 4;
    const float* Bptr = B + (long)(bn + arow) * ldb + acol * 4;

    for (int k0 = 0; k0 < K; k0 += 16) {
        float4 a0 = *(const float4*)(Aptr + k0);
        float4 a1 = *(const float4*)(Aptr + (long)64 * lda + k0);
        float4 b0 = *(const float4*)(Bptr + k0);
        __syncthreads();
        As[acol * 4 + 0][arow] = a0.x; As[acol * 4 + 1][arow] = a0.y;
        As[acol * 4 + 2][arow] = a0.z; As[acol * 4 + 3][arow] = a0.w;
        As[acol * 4 + 0][arow + 64] = a1.x; As[acol * 4 + 1][arow + 64] = a1.y;
        As[acol * 4 + 2][arow + 64] = a1.z; As[acol * 4 + 3][arow + 64] = a1.w;
        Bs[acol * 4 + 0][arow] = b0.x; Bs[acol * 4 + 1][arow] = b0.y;
        Bs[acol * 4 + 2][arow] = b0.z; Bs[acol * 4 + 3][arow] = b0.w;
        __syncthreads();
#pragma unroll
        for (int k = 0; k < 16; k++) {
            float4 av0 = *(float4*)&As[k][ty * 8];
            float4 av1 = *(float4*)&As[k][ty * 8 + 4];
            float4 bv  = *(float4*)&Bs[k][tx * 4];
            float a[8] = {av0.x, av0.y, av0.z, av0.w, av1.x, av1.y, av1.z, av1.w};
            float b[4] = {bv.x, bv.y, bv.z, bv.w};
#pragma unroll
            for (int i = 0; i < 8; i++)
#pragma unroll
                for (int j = 0; j < 4; j++) acc[i][j] = fmaf(a[i], b[j], acc[i][j]);
        }
    }
    float4 bb = *(const float4*)(bias + bn + tx * 4);
#pragma unroll
    for (int i = 0; i < 8; i++) {
        float4 o;
        o.x = acc[i][0] + bb.x; o.y = acc[i][1] + bb.y;
        o.z = acc[i][2] + bb.z; o.w = acc[i][3] + bb.w;
        *(float4*)(C + (long)(bm + ty * 8 + i) * ldc + bn + tx * 4) = o;
    }
}

// ---------------- LSTM recurrence: cluster-of-2 gate split, batch-partitioned ----------------
// Each cluster: one (direction, batch-chunk of R rows). CTA rank owns 256 gates.
// Weights fp32 in smem, [kb][gate] float4 layout (conflict-free). One cluster.sync/step,
// gate halves pulled from peer via DSMEM, double-buffered.
template <int R, int NDIR, bool WRITE_ALL>
__global__ __launch_bounds__(256, 1) __cluster_dims__(2, 1, 1)
void lstm_scan_kernel(const float* __restrict__ xg, int gst,
                      const float* __restrict__ whh_f, const float* __restrict__ whh_r,
                      float* __restrict__ out) {
    extern __shared__ float smem[];
    float4* Wsh4 = (float4*)smem;           // [32][256] float4  = 128KB
    float*  Hsh  = smem + 32 * 256 * 4;     // [R][128]
    float*  Gbuf = Hsh + R * 128;           // [2][R][256]

    const int tid = threadIdx.x;
    const uint32_t rank = ctarank();
    const int cluster_id = blockIdx.x >> 1;
    int dir, chunk;
    if (NDIR == 2) { dir = cluster_id & 1; chunk = cluster_id >> 1; }
    else           { dir = 0;              chunk = cluster_id; }
    const int row0 = chunk * R;
    const float* whh = (dir == 0) ? whh_f : whh_r;
    const int gbase = (int)rank * 256;
    const int goff = (NDIR == 2) ? dir * 512 : 0;

    // load 256x128 fp32 weights into smem, [kb][gate] float4 blocks
    for (int i = tid; i < 256 * 32; i += 256) {
        int lg = i >> 5, kb = i & 31;
        float4 v = *(const float4*)(whh + (gbase + lg) * 128 + kb * 4);
        Wsh4[kb * 256 + lg] = v;
    }
    for (int i = tid; i < R * 128; i += 256) Hsh[i] = 0.f;
    __syncthreads();

    uint32_t gb_local = smem_u32(Gbuf);
    uint32_t gb0 = mapa_sh(gb_local, 0);
    uint32_t gb1 = mapa_sh(gb_local, 1);

    const int lg = tid;  // local gate index
    float creg[R / 2];
#pragma unroll
    for (int u = 0; u < R / 2; u++) creg[u] = 0.f;

    for (int s = 0; s < T_SEQ; s++) {
        const int t = (dir == 0) ? s : (T_SEQ - 1 - s);
        const int p = s & 1;
        // prefetch xg (precomputed input gates incl. both biases)
        float xv[R];
#pragma unroll
        for (int r = 0; r < R; r++)
            xv[r] = xg[((row0 + r) * T_SEQ + t) * gst + goff + gbase + lg];
        // gate = w_hh[g,:] . h[r,:]
        float acc[R];
#pragma unroll
        for (int r = 0; r < R; r++) acc[r] = 0.f;
#pragma unroll
        for (int kb = 0; kb < 32; kb++) {
            float4 w = Wsh4[kb * 256 + lg];
#pragma unroll
            for (int r = 0; r < R; r++) {
                float4 h4 = *(const float4*)&Hsh[r * 128 + kb * 4];
                acc[r] = fmaf(w.x, h4.x, fmaf(w.y, h4.y, fmaf(w.z, h4.z, fmaf(w.w, h4.w, acc[r]))));
            }
        }
#pragma unroll
        for (int r = 0; r < R; r++)
            Gbuf[p * (R * 256) + r * 256 + lg] = acc[r] + xv[r];
        CLUSTER_SYNC();  // gate halves visible cluster-wide
        // consume all 4 gates (i,f from rank0, g,o from rank1), update c,h
#pragma unroll
        for (int u = 0; u < R / 2; u++) {
            int rj = tid + u * 256;
            int r = rj >> 7, j = rj & 127;
            uint32_t off = (uint32_t)(p * (R * 256) + r * 256) * 4u;
            float iv = ld_cluster(gb0 + off + (uint32_t)j * 4u);
            float fv = ld_cluster(gb0 + off + (uint32_t)(128 + j) * 4u);
            float gv = ld_cluster(gb1 + off + (uint32_t)j * 4u);
            float ov = ld_cluster(gb1 + off + (uint32_t)(128 + j) * 4u);
            float cN = sigf(fv) * creg[u] + sigf(iv) * tanh_fast(gv);
            creg[u] = cN;
            float h = sigf(ov) * tanh_fast(cN);
            Hsh[r * 128 + j] = h;
            if (rank == 0) {
                if (WRITE_ALL)
                    out[((row0 + r) * T_SEQ + t) * 256 + dir * 128 + j] = h;
                else if (s == T_SEQ - 1)
                    out[(row0 + r) * 256 + j] = h;
            }
        }
        __syncthreads();  // h update visible before next step's gate FMA
    }
    CLUSTER_SYNC();  // don't exit while peer still reads our smem
}

// ---------------- layer1 reverse: single step with h0=0 -> pure elementwise ----------------
__global__ void l1rev_kernel() {
    int idx = blockIdx.x * blockDim.x + threadIdx.x;
    if (idx >= 128 * 128) return;
    int b = idx >> 7, j = idx & 127;
    const float* xg = g_xg1r + b * 512;
    float iv = xg[j], gv = xg[256 + j], ov = xg[384 + j];
    float c = sigf(iv) * tanh_fast(gv);          // f*c0 term is 0
    g_h1last[b * 256 + 128 + j] = sigf(ov) * tanh_fast(c);
}

// ---------------- final FC: out[b][c] = hcat[b] . fc_w[c] + fc_b[c] ----------------
__global__ void fc_kernel(const float* __restrict__ fcw, const float* __restrict__ fcb,
                          float* __restrict__ out) {
    int b = blockIdx.x;
    int lane = threadIdx.x;  // 32
    float v[8];
#pragma unroll
    for (int u = 0; u < 8; u++) v[u] = g_h1last[b * 256 + lane + u * 32];
    for (int c = 0; c < 10; c++) {
        float s = 0.f;
#pragma unroll
        for (int u = 0; u < 8; u++) s = fmaf(v[u], fcw[c * 256 + lane + u * 32], s);
#pragma unroll
        for (int o = 16; o; o >>= 1) s += __shfl_xor_sync(0xffffffffu, s, o);
        if (lane == 0) out[b * 10 + c] = s + fcb[c];
    }
}

// ---------------- launch ----------------
extern "C" void kernel_launch(void* const* d_in, const int* in_sizes, int n_in,
                              void* d_out, int out_size) {
    const int*   x        = (const int*)d_in[0];
    const float* emb      = (const float*)d_in[1];
    const float* wih_l0f  = (const float*)d_in[2];
    const float* whh_l0f  = (const float*)d_in[3];
    const float* bih_l0f  = (const float*)d_in[4];
    const float* bhh_l0f  = (const float*)d_in[5];
    const float* wih_l0r  = (const float*)d_in[6];
    const float* whh_l0r  = (const float*)d_in[7];
    const float* bih_l0r  = (const float*)d_in[8];
    const float* bhh_l0r  = (const float*)d_in[9];
    const float* wih_l1f  = (const float*)d_in[10];
    const float* whh_l1f  = (const float*)d_in[11];
    const float* bih_l1f  = (const float*)d_in[12];
    const float* bhh_l1f  = (const float*)d_in[13];
    const float* wih_l1r  = (const float*)d_in[14];
    const float* bih_l1r  = (const float*)d_in[16];
    const float* bhh_l1r  = (const float*)d_in[17];
    const float* fc_w     = (const float*)d_in[18];
    const float* fc_b     = (const float*)d_in[19];
    float* out = (float*)d_out;

    float *pX0, *pWpad, *pB0, *pB1f, *pB1r, *pXg0, *pHs0, *pXg1f, *pXg1r, *pH1;
    cudaGetSymbolAddress((void**)&pX0,   g_X0);
    cudaGetSymbolAddress((void**)&pWpad, g_Wpad);
    cudaGetSymbolAddress((void**)&pB0,   g_bias0);
    cudaGetSymbolAddress((void**)&pB1f,  g_bias1f);
    cudaGetSymbolAddress((void**)&pB1r,  g_bias1r);
    cudaGetSymbolAddress((void**)&pXg0,  g_xg0);
    cudaGetSymbolAddress((void**)&pHs0,  g_hs0);
    cudaGetSymbolAddress((void**)&pXg1f, g_xg1f);
    cudaGetSymbolAddress((void**)&pXg1r, g_xg1r);
    cudaGetSymbolAddress((void**)&pH1,   g_h1last);

    const int SMEM_R4 = (32 * 256 * 4 + 4 * 128 + 2 * 4 * 256) * 4;   // 141312 B
    const int SMEM_R2 = (32 * 256 * 4 + 2 * 128 + 2 * 2 * 256) * 4;   // 136192 B
    cudaFuncSetAttribute(lstm_scan_kernel<4, 2, true>,
                         cudaFuncAttributeMaxDynamicSharedMemorySize, SMEM_R4);
    cudaFuncSetAttribute(lstm_scan_kernel<2, 1, false>,
                         cudaFuncAttributeMaxDynamicSharedMemorySize, SMEM_R2);

    prep_kernel<<<128, 256>>>(wih_l0f, wih_l0r, bih_l0f, bhh_l0f, bih_l0r, bhh_l0r,
                              bih_l1f, bhh_l1f, bih_l1r, bhh_l1r);
    embed_kernel<<<2048, 256>>>(x, emb);

    // layer 0 input gates, both directions: [65536,304] x [1024,304]^T
    {
        dim3 grid(1024 / 64, MTOT / 128);
        gemm_bias_kernel<<<grid, 256>>>(pX0, KPAD, pWpad, KPAD, pXg0, 1024, KPAD, pB0);
    }
    // layer 0 scan (both dirs concurrently): 64 clusters x 2 CTAs
    lstm_scan_kernel<4, 2, true><<<128, 256, SMEM_R4>>>(pXg0, 1024, whh_l0f, whh_l0r, pHs0);

    // layer 1 forward input gates: [65536,256] x [512,256]^T
    {
        dim3 grid(512 / 64, MTOT / 128);
        gemm_bias_kernel<<<grid, 256>>>(pHs0, 256, wih_l1f, 256, pXg1f, 512, 256, pB1f);
    }
    // layer 1 reverse: only the t=T-1 row is needed -> tiny GEMM (M=128)
    {
        dim3 grid(512 / 64, 1);
        gemm_bias_kernel<<<grid, 256>>>(pHs0 + 511 * 256, T_SEQ * 256, wih_l1r, 256,
                                        pXg1r, 512, 256, pB1r);
    }
    // layer 1 forward scan (only final h needed): 64 clusters x 2 CTAs
    lstm_scan_kernel<2, 1, false><<<128, 256, SMEM_R2>>>(pXg1f, 512, whh_l1f, whh_l1f, pH1);
    // layer 1 reverse: single step, elementwise
    l1rev_kernel<<<64, 256>>>();

    fc_kernel<<<128, 32>>>(fc_w, fc_b, out);
    (void)in_sizes; (void)n_in; (void)out_size;
}

// round 5
// speedup vs baseline: 1.2487x; 1.2487x over previous
#include <cuda_runtime.h>
#include <cstdint>

#define T_SEQ 512
#define B_SZ  128
#define HID   128
#define DEMB  300
#define KPAD  304     // padded to multiple of 16
#define MTOT  65536   // B*T

// single dynamic-smem symbol shared by all dynamic-smem kernels
extern __shared__ char k_smem[];

// ---------------- scratch (device globals; zero-init BSS) ----------------
__device__ float g_X0[MTOT * KPAD];        // padded embedded input, tf32-rounded
__device__ float g_Wpad[1024 * KPAD];      // concat(w_ih_l0f, w_ih_l0r), padded, tf32-rounded
__device__ float g_W1[512 * 256];          // w_ih_l1f, tf32-rounded
__device__ float g_bias0[1024];
__device__ float g_bias1f[512];
__device__ float g_bias1r[512];
__device__ float g_xg0[MTOT * 1024];       // layer0 input gates, both dirs
__device__ float g_hs0[MTOT * 256];        // layer0 output [b][t][fwd128|rev128] (tf32-rounded)
__device__ float g_xg1f[MTOT * 512];
__device__ float g_xg1r[128 * 512];
__device__ float g_h1last[128 * 256];      // [fwd h_T-1 | rev h_at_T-1]

// ---------------- helpers ----------------
__device__ __forceinline__ float sigf(float x) {
    return __fdividef(1.f, 1.f + __expf(-x));
}
__device__ __forceinline__ float tanh_fast(float x) {
    return 1.f - __fdividef(2.f, __expf(2.f * x) + 1.f);
}
__device__ __forceinline__ float rtf32(float x) {
    uint32_t u;
    asm("cvt.rna.tf32.f32 %0, %1;" : "=r"(u) : "f"(x));
    return __uint_as_float(u);
}
__device__ __forceinline__ uint32_t smem_u32(const void* p) {
    uint32_t a;
    asm("{ .reg .u64 t; cvta.to.shared.u64 t, %1; cvt.u32.u64 %0, t; }" : "=r"(a) : "l"(p));
    return a;
}
__device__ __forceinline__ uint32_t mapa_sh(uint32_t a, uint32_t rank) {
    uint32_t o;
    asm("mapa.shared::cluster.u32 %0, %1, %2;" : "=r"(o) : "r"(a), "r"(rank));
    return o;
}
__device__ __forceinline__ float ld_cluster(uint32_t a) {
    float v;
    asm volatile("ld.shared::cluster.f32 %0, [%1];" : "=f"(v) : "r"(a));
    return v;
}
__device__ __forceinline__ uint32_t ctarank() {
    uint32_t r;
    asm("mov.u32 %0, %%cluster_ctarank;" : "=r"(r));
    return r;
}
#define CLUSTER_SYNC() do { \
    asm volatile("barrier.cluster.arrive.aligned;" ::: "memory"); \
    asm volatile("barrier.cluster.wait.aligned;" ::: "memory");   \
} while (0)

__device__ __forceinline__ void cp16(void* s, const void* g) {
    uint32_t sa = smem_u32(s);
    asm volatile("cp.async.cg.shared.global [%0], [%1], 16;" :: "r"(sa), "l"(g));
}
#define CP_COMMIT() asm volatile("cp.async.commit_group;" ::: "memory")
#define CP_WAIT0()  asm volatile("cp.async.wait_group 0;" ::: "memory")

__device__ __forceinline__ void mma_tf32(float* c, const uint32_t* a,
                                         uint32_t b0, uint32_t b1) {
    asm volatile(
        "mma.sync.aligned.m16n8k8.row.col.f32.tf32.tf32.f32 "
        "{%0,%1,%2,%3}, {%4,%5,%6,%7}, {%8,%9}, {%0,%1,%2,%3};"
        : "+f"(c[0]), "+f"(c[1]), "+f"(c[2]), "+f"(c[3])
        : "r"(a[0]), "r"(a[1]), "r"(a[2]), "r"(a[3]), "r"(b0), "r"(b1));
}

// ---------------- prep: pad + tf32-round weights, combine biases ----------------
__global__ void prep_kernel(const float* __restrict__ wf, const float* __restrict__ wr,
                            const float* __restrict__ w1f,
                            const float* __restrict__ bif, const float* __restrict__ bhf,
                            const float* __restrict__ bir, const float* __restrict__ bhr,
                            const float* __restrict__ b1if, const float* __restrict__ b1hf,
                            const float* __restrict__ b1ir, const float* __restrict__ b1hr) {
    int idx = blockIdx.x * blockDim.x + threadIdx.x;
    int stride = gridDim.x * blockDim.x;
    for (int i = idx; i < 1024 * KPAD; i += stride) {
        int n = i / KPAD, k = i - n * KPAD;
        float v = 0.f;
        if (k < DEMB) v = (n < 512) ? wf[n * DEMB + k] : wr[(n - 512) * DEMB + k];
        g_Wpad[i] = rtf32(v);
    }
    for (int i = idx; i < 512 * 256; i += stride) g_W1[i] = rtf32(w1f[i]);
    if (idx < 1024)
        g_bias0[idx] = (idx < 512) ? (bif[idx] + bhf[idx]) : (bir[idx - 512] + bhr[idx - 512]);
    if (idx < 512) {
        g_bias1f[idx] = b1if[idx] + b1hf[idx];
        g_bias1r[idx] = b1ir[idx] + b1hr[idx];
    }
}

// ---------------- embedding gather (tf32-rounded store) ----------------
__global__ void embed_kernel(const int* __restrict__ x, const float* __restrict__ emb) {
    int idx = blockIdx.x * blockDim.x + threadIdx.x;
    int stride = gridDim.x * blockDim.x;
    const int total = MTOT * 75;  // 75 float4 per row (300 floats); cols 300..303 stay 0
    for (int i = idx; i < total; i += stride) {
        int m = i / 75, q = i - m * 75;
        int v = x[m];
        float4 val = *(const float4*)(emb + (long)v * DEMB + q * 4);
        float4 w = make_float4(rtf32(val.x), rtf32(val.y), rtf32(val.z), rtf32(val.w));
        *(float4*)(g_X0 + (long)m * KPAD + q * 4) = w;
    }
}

// ---------------- tensor-core tf32 GEMM (base-ISA mma.sync) ----------------
// C[m][n] = sum_k A[m][k]*B[n][k] + bias[n].  A:[M,lda] B:[N,ldb] row-major.
// BM=128, BN=128, BK=16, 256 thr = 8 warps (4m x 2n), warp tile 32x64 (2x8 m16n8k8).
// Operands must already be tf32-exact (pre-rounded) — HW truncation is then lossless.
#define PAD_K 20
__global__ __launch_bounds__(256) void gemm_mma_kernel(
    const float* __restrict__ A, int lda,
    const float* __restrict__ B, int ldb,
    float* __restrict__ C, int ldc,
    int K, const float* __restrict__ bias) {
    __shared__ float As[2][128 * PAD_K];
    __shared__ float Bs[2][128 * PAD_K];

    const int tid = threadIdx.x;
    const int lane = tid & 31, wid = tid >> 5;
    const int wm = wid >> 1, wn = wid & 1;        // 4 x 2 warp grid
    const int g = lane >> 2, t = lane & 3;
    const int bm = blockIdx.y * 128, bn = blockIdx.x * 128;

    float c[2][8][4];
#pragma unroll
    for (int mt = 0; mt < 2; mt++)
#pragma unroll
        for (int nt = 0; nt < 8; nt++)
#pragma unroll
            for (int j = 0; j < 4; j++) c[mt][nt][j] = 0.f;

    const int nit = K / 16;
    // stage loader: 512 float4 for A + 512 for B, 256 threads -> 2+2 each
    auto load_stage = [&](int it, int p) {
#pragma unroll
        for (int i = tid; i < 512; i += 256) {
            int r = i >> 2, q = i & 3;
            cp16(&As[p][r * PAD_K + q * 4], A + (long)(bm + r) * lda + it * 16 + q * 4);
        }
#pragma unroll
        for (int i = tid; i < 512; i += 256) {
            int r = i >> 2, q = i & 3;
            cp16(&Bs[p][r * PAD_K + q * 4], B + (long)(bn + r) * ldb + it * 16 + q * 4);
        }
        CP_COMMIT();
    };

    load_stage(0, 0);
    for (int it = 0; it < nit; it++) {
        CP_WAIT0();
        __syncthreads();
        if (it + 1 < nit) load_stage(it + 1, (it + 1) & 1);
        const int p = it & 1;
        const float* Ab = As[p] + (wm * 32) * PAD_K;
        const float* Bb = Bs[p] + (wn * 64) * PAD_K;
#pragma unroll
        for (int ks = 0; ks < 2; ks++) {
            const int k0 = ks * 8;
            uint32_t afr[2][4];
#pragma unroll
            for (int mt = 0; mt < 2; mt++) {
                const float* r0 = Ab + (mt * 16 + g) * PAD_K + k0 + t;
                const float* r1 = r0 + 8 * PAD_K;
                afr[mt][0] = __float_as_uint(r0[0]);
                afr[mt][1] = __float_as_uint(r1[0]);
                afr[mt][2] = __float_as_uint(r0[4]);
                afr[mt][3] = __float_as_uint(r1[4]);
            }
#pragma unroll
            for (int nt = 0; nt < 8; nt++) {
                const float* br = Bb + (nt * 8 + g) * PAD_K + k0 + t;
                uint32_t b0 = __float_as_uint(br[0]);
                uint32_t b1 = __float_as_uint(br[4]);
                mma_tf32(c[0][nt], afr[0], b0, b1);
                mma_tf32(c[1][nt], afr[1], b0, b1);
            }
        }
        __syncthreads();
    }

    // epilogue
#pragma unroll
    for (int mt = 0; mt < 2; mt++) {
        const int row = bm + wm * 32 + mt * 16 + g;
#pragma unroll
        for (int nt = 0; nt < 8; nt++) {
            const int col = bn + wn * 64 + nt * 8 + 2 * t;
            float2 bb = *(const float2*)(bias + col);
            float2 o0 = make_float2(c[mt][nt][0] + bb.x, c[mt][nt][1] + bb.y);
            float2 o1 = make_float2(c[mt][nt][2] + bb.x, c[mt][nt][3] + bb.y);
            *(float2*)(C + (long)row * ldc + col) = o0;
            *(float2*)(C + (long)(row + 8) * ldc + col) = o1;
        }
    }
}

// ---------------- fp32 tiled GEMM (tiny layer-1 reverse GEMM only) ----------------
__global__ __launch_bounds__(256) void gemm_bias_kernel(
    const float* __restrict__ A, int lda,
    const float* __restrict__ B, int ldb,
    float* __restrict__ C, int ldc,
    int K, const float* __restrict__ bias) {
    __shared__ float As[16][132];
    __shared__ float Bs[16][68];

    const int tid = threadIdx.x;
    const int bm = blockIdx.y * 128, bn = blockIdx.x * 64;
    const int tx = tid & 15, ty = tid >> 4;
    const int arow = tid >> 2, acol = tid & 3;

    float acc[8][4];
#pragma unroll
    for (int i = 0; i < 8; i++)
#pragma unroll
        for (int j = 0; j < 4; j++) acc[i][j] = 0.f;

    const float* Aptr = A + (long)(bm + arow) * lda + acol * 4;
    const float* Bptr = B + (long)(bn + arow) * ldb + acol * 4;

    for (int k0 = 0; k0 < K; k0 += 16) {
        float4 a0 = *(const float4*)(Aptr + k0);
        float4 a1 = *(const float4*)(Aptr + (long)64 * lda + k0);
        float4 b0 = *(const float4*)(Bptr + k0);
        __syncthreads();
        As[acol * 4 + 0][arow] = a0.x; As[acol * 4 + 1][arow] = a0.y;
        As[acol * 4 + 2][arow] = a0.z; As[acol * 4 + 3][arow] = a0.w;
        As[acol * 4 + 0][arow + 64] = a1.x; As[acol * 4 + 1][arow + 64] = a1.y;
        As[acol * 4 + 2][arow + 64] = a1.z; As[acol * 4 + 3][arow + 64] = a1.w;
        Bs[acol * 4 + 0][arow] = b0.x; Bs[acol * 4 + 1][arow] = b0.y;
        Bs[acol * 4 + 2][arow] = b0.z; Bs[acol * 4 + 3][arow] = b0.w;
        __syncthreads();
#pragma unroll
        for (int k = 0; k < 16; k++) {
            float4 av0 = *(float4*)&As[k][ty * 8];
            float4 av1 = *(float4*)&As[k][ty * 8 + 4];
            float4 bv  = *(float4*)&Bs[k][tx * 4];
            float a[8] = {av0.x, av0.y, av0.z, av0.w, av1.x, av1.y, av1.z, av1.w};
            float b[4] = {bv.x, bv.y, bv.z, bv.w};
#pragma unroll
            for (int i = 0; i < 8; i++)
#pragma unroll
                for (int j = 0; j < 4; j++) acc[i][j] = fmaf(a[i], b[j], acc[i][j]);
        }
    }
    float4 bb = *(const float4*)(bias + bn + tx * 4);
#pragma unroll
    for (int i = 0; i < 8; i++) {
        float4 o;
        o.x = acc[i][0] + bb.x; o.y = acc[i][1] + bb.y;
        o.z = acc[i][2] + bb.z; o.w = acc[i][3] + bb.w;
        *(float4*)(C + (long)(bm + ty * 8 + i) * ldc + bn + tx * 4) = o;
    }
}

// ---------------- LSTM recurrence: cluster-of-2 gate split, batch-partitioned ----------------
template <int R, int NDIR, bool WRITE_ALL>
__global__ __launch_bounds__(256, 1) __cluster_dims__(2, 1, 1)
void lstm_scan_kernel(const float* __restrict__ xg, int gst,
                      const float* __restrict__ whh_f, const float* __restrict__ whh_r,
                      float* __restrict__ out) {
    float* smem = (float*)k_smem;
    float4* Wsh4 = (float4*)smem;           // [32][256] float4  = 128KB
    float*  Hsh  = smem + 32 * 256 * 4;     // [R][128]
    float*  Gbuf = Hsh + R * 128;           // [2][R][256]

    const int tid = threadIdx.x;
    const uint32_t rank = ctarank();
    const int cluster_id = blockIdx.x >> 1;
    int dir, chunk;
    if (NDIR == 2) { dir = cluster_id & 1; chunk = cluster_id >> 1; }
    else           { dir = 0;              chunk = cluster_id; }
    const int row0 = chunk * R;
    const float* whh = (dir == 0) ? whh_f : whh_r;
    const int gbase = (int)rank * 256;
    const int goff = (NDIR == 2) ? dir * 512 : 0;

    for (int i = tid; i < 256 * 32; i += 256) {
        int lg = i >> 5, kb = i & 31;
        float4 v = *(const float4*)(whh + (gbase + lg) * 128 + kb * 4);
        Wsh4[kb * 256 + lg] = v;
    }
    for (int i = tid; i < R * 128; i += 256) Hsh[i] = 0.f;
    __syncthreads();

    uint32_t gb_local = smem_u32(Gbuf);
    uint32_t gb0 = mapa_sh(gb_local, 0);
    uint32_t gb1 = mapa_sh(gb_local, 1);

    const int lg = tid;
    float creg[R / 2];
#pragma unroll
    for (int u = 0; u < R / 2; u++) creg[u] = 0.f;

    for (int s = 0; s < T_SEQ; s++) {
        const int t = (dir == 0) ? s : (T_SEQ - 1 - s);
        const int p = s & 1;
        float xv[R];
#pragma unroll
        for (int r = 0; r < R; r++)
            xv[r] = xg[((row0 + r) * T_SEQ + t) * gst + goff + gbase + lg];
        float acc[R];
#pragma unroll
        for (int r = 0; r < R; r++) acc[r] = 0.f;
#pragma unroll
        for (int kb = 0; kb < 32; kb++) {
            float4 w = Wsh4[kb * 256 + lg];
#pragma unroll
            for (int r = 0; r < R; r++) {
                float4 h4 = *(const float4*)&Hsh[r * 128 + kb * 4];
                acc[r] = fmaf(w.x, h4.x, fmaf(w.y, h4.y, fmaf(w.z, h4.z, fmaf(w.w, h4.w, acc[r]))));
            }
        }
#pragma unroll
        for (int r = 0; r < R; r++)
            Gbuf[p * (R * 256) + r * 256 + lg] = acc[r] + xv[r];
        CLUSTER_SYNC();
#pragma unroll
        for (int u = 0; u < R / 2; u++) {
            int rj = tid + u * 256;
            int r = rj >> 7, j = rj & 127;
            uint32_t off = (uint32_t)(p * (R * 256) + r * 256) * 4u;
            float iv = ld_cluster(gb0 + off + (uint32_t)j * 4u);
            float fv = ld_cluster(gb0 + off + (uint32_t)(128 + j) * 4u);
            float gv = ld_cluster(gb1 + off + (uint32_t)j * 4u);
            float ov = ld_cluster(gb1 + off + (uint32_t)(128 + j) * 4u);
            float cN = sigf(fv) * creg[u] + sigf(iv) * tanh_fast(gv);
            creg[u] = cN;
            float h = sigf(ov) * tanh_fast(cN);
            Hsh[r * 128 + j] = h;
            if (rank == 0) {
                if (WRITE_ALL)
                    out[((row0 + r) * T_SEQ + t) * 256 + dir * 128 + j] = rtf32(h);
                else if (s == T_SEQ - 1)
                    out[(row0 + r) * 256 + j] = h;
            }
        }
        __syncthreads();
    }
    CLUSTER_SYNC();
}

// ---------------- layer1 reverse: single step with h0=0 -> pure elementwise ----------------
__global__ void l1rev_kernel() {
    int idx = blockIdx.x * blockDim.x + threadIdx.x;
    if (idx >= 128 * 128) return;
    int b = idx >> 7, j = idx & 127;
    const float* xg = g_xg1r + b * 512;
    float iv = xg[j], gv = xg[256 + j], ov = xg[384 + j];
    float c = sigf(iv) * tanh_fast(gv);
    g_h1last[b * 256 + 128 + j] = sigf(ov) * tanh_fast(c);
}

// ---------------- final FC ----------------
__global__ void fc_kernel(const float* __restrict__ fcw, const float* __restrict__ fcb,
                          float* __restrict__ out) {
    int b = blockIdx.x;
    int lane = threadIdx.x;
    float v[8];
#pragma unroll
    for (int u = 0; u < 8; u++) v[u] = g_h1last[b * 256 + lane + u * 32];
    for (int c = 0; c < 10; c++) {
        float s = 0.f;
#pragma unroll
        for (int u = 0; u < 8; u++) s = fmaf(v[u], fcw[c * 256 + lane + u * 32], s);
#pragma unroll
        for (int o = 16; o; o >>= 1) s += __shfl_xor_sync(0xffffffffu, s, o);
        if (lane == 0) out[b * 10 + c] = s + fcb[c];
    }
}

// ---------------- launch ----------------
extern "C" void kernel_launch(void* const* d_in, const int* in_sizes, int n_in,
                              void* d_out, int out_size) {
    const int*   x        = (const int*)d_in[0];
    const float* emb      = (const float*)d_in[1];
    const float* wih_l0f  = (const float*)d_in[2];
    const float* whh_l0f  = (const float*)d_in[3];
    const float* bih_l0f  = (const float*)d_in[4];
    const float* bhh_l0f  = (const float*)d_in[5];
    const float* wih_l0r  = (const float*)d_in[6];
    const float* whh_l0r  = (const float*)d_in[7];
    const float* bih_l0r  = (const float*)d_in[8];
    const float* bhh_l0r  = (const float*)d_in[9];
    const float* wih_l1f  = (const float*)d_in[10];
    const float* whh_l1f  = (const float*)d_in[11];
    const float* bih_l1f  = (const float*)d_in[12];
    const float* bhh_l1f  = (const float*)d_in[13];
    const float* wih_l1r  = (const float*)d_in[14];
    const float* bih_l1r  = (const float*)d_in[16];
    const float* bhh_l1r  = (const float*)d_in[17];
    const float* fc_w     = (const float*)d_in[18];
    const float* fc_b     = (const float*)d_in[19];
    float* out = (float*)d_out;

    float *pX0, *pWpad, *pW1, *pB0, *pB1f, *pB1r, *pXg0, *pHs0, *pXg1f, *pXg1r;
    cudaGetSymbolAddress((void**)&pX0,   g_X0);
    cudaGetSymbolAddress((void**)&pWpad, g_Wpad);
    cudaGetSymbolAddress((void**)&pW1,   g_W1);
    cudaGetSymbolAddress((void**)&pB0,   g_bias0);
    cudaGetSymbolAddress((void**)&pB1f,  g_bias1f);
    cudaGetSymbolAddress((void**)&pB1r,  g_bias1r);
    cudaGetSymbolAddress((void**)&pXg0,  g_xg0);
    cudaGetSymbolAddress((void**)&pHs0,  g_hs0);
    cudaGetSymbolAddress((void**)&pXg1f, g_xg1f);
    cudaGetSymbolAddress((void**)&pXg1r, g_xg1r);
    float* pH1;
    cudaGetSymbolAddress((void**)&pH1,   g_h1last);

    const int SMEM_R4 = (32 * 256 * 4 + 4 * 128 + 2 * 4 * 256) * 4;   // 141312 B
    const int SMEM_R2 = (32 * 256 * 4 + 2 * 128 + 2 * 2 * 256) * 4;   // 136192 B
    cudaFuncSetAttribute(lstm_scan_kernel<4, 2, true>,
                         cudaFuncAttributeMaxDynamicSharedMemorySize, SMEM_R4);
    cudaFuncSetAttribute(lstm_scan_kernel<2, 1, false>,
                         cudaFuncAttributeMaxDynamicSharedMemorySize, SMEM_R2);

    prep_kernel<<<128, 256>>>(wih_l0f, wih_l0r, wih_l1f,
                              bih_l0f, bhh_l0f, bih_l0r, bhh_l0r,
                              bih_l1f, bhh_l1f, bih_l1r, bhh_l1r);
    embed_kernel<<<2048, 256>>>(x, emb);

    // layer 0 input gates (tensor cores via mma.sync tf32): [65536,304] x [1024,304]^T
    {
        dim3 grid(1024 / 128, MTOT / 128);
        gemm_mma_kernel<<<grid, 256>>>(pX0, KPAD, pWpad, KPAD, pXg0, 1024, KPAD, pB0);
    }
    // layer 0 scan (both dirs): 64 clusters x 2 CTAs
    lstm_scan_kernel<4, 2, true><<<128, 256, SMEM_R4>>>(pXg0, 1024, whh_l0f, whh_l0r, pHs0);

    // layer 1 forward input gates (tensor cores): [65536,256] x [512,256]^T
    {
        dim3 grid(512 / 128, MTOT / 128);
        gemm_mma_kernel<<<grid, 256>>>(pHs0, 256, pW1, 256, pXg1f, 512, 256, pB1f);
    }
    // layer 1 reverse: only t=T-1 row needed -> tiny GEMM (M=128), fp32 SIMT
    {
        dim3 grid(512 / 64, 1);
        gemm_bias_kernel<<<grid, 256>>>(pHs0 + 511 * 256, T_SEQ * 256, wih_l1r, 256,
                                        pXg1r, 512, 256, pB1r);
    }
    // layer 1 forward scan (only final h needed): 64 clusters x 2 CTAs
    lstm_scan_kernel<2, 1, false><<<128, 256, SMEM_R2>>>(pXg1f, 512, whh_l1f, whh_l1f, pH1);
    // layer 1 reverse: single step, elementwise
    l1rev_kernel<<<64, 256>>>();

    fc_kernel<<<128, 32>>>(fc_w, fc_b, out);
    (void)in_sizes; (void)n_in; (void)out_size;
}

// round 6
// speedup vs baseline: 1.2793x; 1.0245x over previous
#include <cuda_runtime.h>
#include <cstdint>

#define T_SEQ 512
#define B_SZ  128
#define HID   128
#define DEMB  300
#define KPAD  304     // padded to multiple of 16
#define MTOT  65536   // B*T

// single dynamic-smem symbol shared by all dynamic-smem kernels
extern __shared__ char k_smem[];

// ---------------- scratch (device globals; zero-init BSS) ----------------
__device__ float g_X0[MTOT * KPAD];        // padded embedded input, tf32-rounded
__device__ float g_Wpad[1024 * KPAD];      // concat(w_ih_l0f, w_ih_l0r), padded, tf32-rounded
__device__ float g_W1[512 * 256];          // w_ih_l1f, tf32-rounded
__device__ float g_bias0[1024];
__device__ float g_bias1f[512];
__device__ float g_bias1r[512];
__device__ float g_xg0[MTOT * 1024];       // layer0 input gates, both dirs
__device__ float g_hs0[MTOT * 256];        // layer0 output [b][t][fwd128|rev128] (tf32-rounded)
__device__ float g_xg1f[MTOT * 512];
__device__ float g_xg1r[128 * 512];
__device__ float g_h1last[128 * 256];      // [fwd h_T-1 | rev h_at_T-1]

// ---------------- helpers ----------------
__device__ __forceinline__ float sigf(float x) {
    return __fdividef(1.f, 1.f + __expf(-x));
}
__device__ __forceinline__ float tanh_fast(float x) {
    return 1.f - __fdividef(2.f, __expf(2.f * x) + 1.f);
}
__device__ __forceinline__ float rtf32(float x) {
    uint32_t u;
    asm("cvt.rna.tf32.f32 %0, %1;" : "=r"(u) : "f"(x));
    return __uint_as_float(u);
}
__device__ __forceinline__ uint32_t smem_u32(const void* p) {
    uint32_t a;
    asm("{ .reg .u64 t; cvta.to.shared.u64 t, %1; cvt.u32.u64 %0, t; }" : "=r"(a) : "l"(p));
    return a;
}
__device__ __forceinline__ uint32_t mapa_sh(uint32_t a, uint32_t rank) {
    uint32_t o;
    asm("mapa.shared::cluster.u32 %0, %1, %2;" : "=r"(o) : "r"(a), "r"(rank));
    return o;
}
__device__ __forceinline__ float ld_cluster(uint32_t a) {
    float v;
    asm volatile("ld.shared::cluster.f32 %0, [%1];" : "=f"(v) : "r"(a));
    return v;
}
__device__ __forceinline__ uint32_t ctarank() {
    uint32_t r;
    asm("mov.u32 %0, %%cluster_ctarank;" : "=r"(r));
    return r;
}
#define CLUSTER_ARRIVE() asm volatile("barrier.cluster.arrive.aligned;" ::: "memory")
#define CLUSTER_WAIT()   asm volatile("barrier.cluster.wait.aligned;" ::: "memory")
#define CLUSTER_SYNC() do { CLUSTER_ARRIVE(); CLUSTER_WAIT(); } while (0)

// ---- packed f32x2 (Blackwell base ISA; only reachable from PTX) ----
typedef unsigned long long ull_t;
__device__ __forceinline__ ull_t pack2(float x, float y) {
    ull_t r; asm("mov.b64 %0, {%1,%2};" : "=l"(r) : "f"(x), "f"(y)); return r;
}
__device__ __forceinline__ ull_t fma2(ull_t a, ull_t b, ull_t c) {
    ull_t d; asm("fma.rn.f32x2 %0, %1, %2, %3;" : "=l"(d) : "l"(a), "l"(b), "l"(c)); return d;
}
__device__ __forceinline__ ull_t add2(ull_t a, ull_t b) {
    ull_t d; asm("add.rn.f32x2 %0, %1, %2;" : "=l"(d) : "l"(a), "l"(b)); return d;
}

__device__ __forceinline__ void cp16(void* s, const void* g) {
    uint32_t sa = smem_u32(s);
    asm volatile("cp.async.cg.shared.global [%0], [%1], 16;" :: "r"(sa), "l"(g));
}
#define CP_COMMIT() asm volatile("cp.async.commit_group;" ::: "memory")
#define CP_WAIT0()  asm volatile("cp.async.wait_group 0;" ::: "memory")

__device__ __forceinline__ void mma_tf32(float* c, const uint32_t* a,
                                         uint32_t b0, uint32_t b1) {
    asm volatile(
        "mma.sync.aligned.m16n8k8.row.col.f32.tf32.tf32.f32 "
        "{%0,%1,%2,%3}, {%4,%5,%6,%7}, {%8,%9}, {%0,%1,%2,%3};"
        : "+f"(c[0]), "+f"(c[1]), "+f"(c[2]), "+f"(c[3])
        : "r"(a[0]), "r"(a[1]), "r"(a[2]), "r"(a[3]), "r"(b0), "r"(b1));
}

// ---------------- prep: pad + tf32-round weights, combine biases ----------------
__global__ void prep_kernel(const float* __restrict__ wf, const float* __restrict__ wr,
                            const float* __restrict__ w1f,
                            const float* __restrict__ bif, const float* __restrict__ bhf,
                            const float* __restrict__ bir, const float* __restrict__ bhr,
                            const float* __restrict__ b1if, const float* __restrict__ b1hf,
                            const float* __restrict__ b1ir, const float* __restrict__ b1hr) {
    int idx = blockIdx.x * blockDim.x + threadIdx.x;
    int stride = gridDim.x * blockDim.x;
    for (int i = idx; i < 1024 * KPAD; i += stride) {
        int n = i / KPAD, k = i - n * KPAD;
        float v = 0.f;
        if (k < DEMB) v = (n < 512) ? wf[n * DEMB + k] : wr[(n - 512) * DEMB + k];
        g_Wpad[i] = rtf32(v);
    }
    for (int i = idx; i < 512 * 256; i += stride) g_W1[i] = rtf32(w1f[i]);
    if (idx < 1024)
        g_bias0[idx] = (idx < 512) ? (bif[idx] + bhf[idx]) : (bir[idx - 512] + bhr[idx - 512]);
    if (idx < 512) {
        g_bias1f[idx] = b1if[idx] + b1hf[idx];
        g_bias1r[idx] = b1ir[idx] + b1hr[idx];
    }
}

// ---------------- embedding gather (tf32-rounded store) ----------------
__global__ void embed_kernel(const int* __restrict__ x, const float* __restrict__ emb) {
    int idx = blockIdx.x * blockDim.x + threadIdx.x;
    int stride = gridDim.x * blockDim.x;
    const int total = MTOT * 75;  // 75 float4 per row (300 floats); cols 300..303 stay 0
    for (int i = idx; i < total; i += stride) {
        int m = i / 75, q = i - m * 75;
        int v = x[m];
        float4 val = *(const float4*)(emb + (long)v * DEMB + q * 4);
        float4 w = make_float4(rtf32(val.x), rtf32(val.y), rtf32(val.z), rtf32(val.w));
        *(float4*)(g_X0 + (long)m * KPAD + q * 4) = w;
    }
}

// ---------------- tensor-core tf32 GEMM (base-ISA mma.sync) ----------------
#define PAD_K 20
__global__ __launch_bounds__(256) void gemm_mma_kernel(
    const float* __restrict__ A, int lda,
    const float* __restrict__ B, int ldb,
    float* __restrict__ C, int ldc,
    int K, const float* __restrict__ bias) {
    __shared__ float As[2][128 * PAD_K];
    __shared__ float Bs[2][128 * PAD_K];

    const int tid = threadIdx.x;
    const int lane = tid & 31, wid = tid >> 5;
    const int wm = wid >> 1, wn = wid & 1;        // 4 x 2 warp grid
    const int g = lane >> 2, t = lane & 3;
    const int bm = blockIdx.y * 128, bn = blockIdx.x * 128;

    float c[2][8][4];
#pragma unroll
    for (int mt = 0; mt < 2; mt++)
#pragma unroll
        for (int nt = 0; nt < 8; nt++)
#pragma unroll
            for (int j = 0; j < 4; j++) c[mt][nt][j] = 0.f;

    const int nit = K / 16;
    auto load_stage = [&](int it, int p) {
#pragma unroll
        for (int i = tid; i < 512; i += 256) {
            int r = i >> 2, q = i & 3;
            cp16(&As[p][r * PAD_K + q * 4], A + (long)(bm + r) * lda + it * 16 + q * 4);
        }
#pragma unroll
        for (int i = tid; i < 512; i += 256) {
            int r = i >> 2, q = i & 3;
            cp16(&Bs[p][r * PAD_K + q * 4], B + (long)(bn + r) * ldb + it * 16 + q * 4);
        }
        CP_COMMIT();
    };

    load_stage(0, 0);
    for (int it = 0; it < nit; it++) {
        CP_WAIT0();
        __syncthreads();
        if (it + 1 < nit) load_stage(it + 1, (it + 1) & 1);
        const int p = it & 1;
        const float* Ab = As[p] + (wm * 32) * PAD_K;
        const float* Bb = Bs[p] + (wn * 64) * PAD_K;
#pragma unroll
        for (int ks = 0; ks < 2; ks++) {
            const int k0 = ks * 8;
            uint32_t afr[2][4];
#pragma unroll
            for (int mt = 0; mt < 2; mt++) {
                const float* r0 = Ab + (mt * 16 + g) * PAD_K + k0 + t;
                const float* r1 = r0 + 8 * PAD_K;
                afr[mt][0] = __float_as_uint(r0[0]);
                afr[mt][1] = __float_as_uint(r1[0]);
                afr[mt][2] = __float_as_uint(r0[4]);
                afr[mt][3] = __float_as_uint(r1[4]);
            }
#pragma unroll
            for (int nt = 0; nt < 8; nt++) {
                const float* br = Bb + (nt * 8 + g) * PAD_K + k0 + t;
                uint32_t b0 = __float_as_uint(br[0]);
                uint32_t b1 = __float_as_uint(br[4]);
                mma_tf32(c[0][nt], afr[0], b0, b1);
                mma_tf32(c[1][nt], afr[1], b0, b1);
            }
        }
        __syncthreads();
    }

#pragma unroll
    for (int mt = 0; mt < 2; mt++) {
        const int row = bm + wm * 32 + mt * 16 + g;
#pragma unroll
        for (int nt = 0; nt < 8; nt++) {
            const int col = bn + wn * 64 + nt * 8 + 2 * t;
            float2 bb = *(const float2*)(bias + col);
            float2 o0 = make_float2(c[mt][nt][0] + bb.x, c[mt][nt][1] + bb.y);
            float2 o1 = make_float2(c[mt][nt][2] + bb.x, c[mt][nt][3] + bb.y);
            *(float2*)(C + (long)row * ldc + col) = o0;
            *(float2*)(C + (long)(row + 8) * ldc + col) = o1;
        }
    }
}

// ---------------- fp32 tiled GEMM (tiny layer-1 reverse GEMM only) ----------------
__global__ __launch_bounds__(256) void gemm_bias_kernel(
    const float* __restrict__ A, int lda,
    const float* __restrict__ B, int ldb,
    float* __restrict__ C, int ldc,
    int K, const float* __restrict__ bias) {
    __shared__ float As[16][132];
    __shared__ float Bs[16][68];

    const int tid = threadIdx.x;
    const int bm = blockIdx.y * 128, bn = blockIdx.x * 64;
    const int tx = tid & 15, ty = tid >> 4;
    const int arow = tid >> 2, acol = tid & 3;

    float acc[8][4];
#pragma unroll
    for (int i = 0; i < 8; i++)
#pragma unroll
        for (int j = 0; j < 4; j++) acc[i][j] = 0.f;

    const float* Aptr = A + (long)(bm + arow) * lda + acol * 4;
    const float* Bptr = B + (long)(bn + arow) * ldb + acol * 4;

    for (int k0 = 0; k0 < K; k0 += 16) {
        float4 a0 = *(const float4*)(Aptr + k0);
        float4 a1 = *(const float4*)(Aptr + (long)64 * lda + k0);
        float4 b0 = *(const float4*)(Bptr + k0);
        __syncthreads();
        As[acol * 4 + 0][arow] = a0.x; As[acol * 4 + 1][arow] = a0.y;
        As[acol * 4 + 2][arow] = a0.z; As[acol * 4 + 3][arow] = a0.w;
        As[acol * 4 + 0][arow + 64] = a1.x; As[acol * 4 + 1][arow + 64] = a1.y;
        As[acol * 4 + 2][arow + 64] = a1.z; As[acol * 4 + 3][arow + 64] = a1.w;
        Bs[acol * 4 + 0][arow] = b0.x; Bs[acol * 4 + 1][arow] = b0.y;
        Bs[acol * 4 + 2][arow] = b0.z; Bs[acol * 4 + 3][arow] = b0.w;
        __syncthreads();
#pragma unroll
        for (int k = 0; k < 16; k++) {
            float4 av0 = *(float4*)&As[k][ty * 8];
            float4 av1 = *(float4*)&As[k][ty * 8 + 4];
            float4 bv  = *(float4*)&Bs[k][tx * 4];
            float a[8] = {av0.x, av0.y, av0.z, av0.w, av1.x, av1.y, av1.z, av1.w};
            float b[4] = {bv.x, bv.y, bv.z, bv.w};
#pragma unroll
            for (int i = 0; i < 8; i++)
#pragma unroll
                for (int j = 0; j < 4; j++) acc[i][j] = fmaf(a[i], b[j], acc[i][j]);
        }
    }
    float4 bb = *(const float4*)(bias + bn + tx * 4);
#pragma unroll
    for (int i = 0; i < 8; i++) {
        float4 o;
        o.x = acc[i][0] + bb.x; o.y = acc[i][1] + bb.y;
        o.z = acc[i][2] + bb.z; o.w = acc[i][3] + bb.w;
        *(float4*)(C + (long)(bm + ty * 8 + i) * ldc + bn + tx * 4) = o;
    }
}

// ---------------- LSTM recurrence: f32x2-packed matvec, cluster-of-2 gate split ----------------
// CTA rank owns 256 gates. Weights in smem [kb][gate] float4 (over k). h stored
// transposed [k][R] so a row-pair loads as half of one LDS.128. Gates stored as
// packed row-pairs (STS.64). Per-step sync: cluster arrive / xg-prefetch / wait.
template <int R, int NDIR, bool WRITE_ALL>
__global__ __launch_bounds__(256, 1) __cluster_dims__(2, 1, 1)
void lstm_scan_kernel(const float* __restrict__ xg, int gst,
                      const float* __restrict__ whh_f, const float* __restrict__ whh_r,
                      float* __restrict__ out) {
    float* smem = (float*)k_smem;
    float4* Wsh4 = (float4*)smem;           // [32][256] float4 = 128KB
    float*  HshT = smem + 32 * 256 * 4;     // [128][R] transposed h
    float*  Gbuf = HshT + 128 * R;          // [2][R/2][256][2] packed gates

    const int tid = threadIdx.x;
    const uint32_t rank = ctarank();
    const int cluster_id = blockIdx.x >> 1;
    int dir, chunk;
    if (NDIR == 2) { dir = cluster_id & 1; chunk = cluster_id >> 1; }
    else           { dir = 0;              chunk = cluster_id; }
    const int row0 = chunk * R;
    const float* whh = (dir == 0) ? whh_f : whh_r;
    const int gbase = (int)rank * 256;
    const int goff = (NDIR == 2) ? dir * 512 : 0;
    const int RP = R / 2;

    // load weights: [kb][gate] float4 blocks (w for k=4kb..4kb+3 of gate lg)
    for (int i = tid; i < 256 * 32; i += 256) {
        int lg = i >> 5, kb = i & 31;
        float4 v = *(const float4*)(whh + (gbase + lg) * 128 + kb * 4);
        Wsh4[kb * 256 + lg] = v;
    }
    for (int i = tid; i < 128 * R; i += 256) HshT[i] = 0.f;
    __syncthreads();

    const uint32_t gb_local = smem_u32(Gbuf);
    const uint32_t gb0 = mapa_sh(gb_local, 0);
    const uint32_t gb1 = mapa_sh(gb_local, 1);

    const int lg = tid;  // local gate index
    float creg[R / 2 < 1 ? 1 : R / 2];
#pragma unroll
    for (int u = 0; u < R / 2; u++) creg[u] = 0.f;

    // preload xg for step 0
    float xv[R];
    {
        const int t0 = (dir == 0) ? 0 : (T_SEQ - 1);
#pragma unroll
        for (int r = 0; r < R; r++)
            xv[r] = xg[((row0 + r) * T_SEQ + t0) * gst + goff + gbase + lg];
    }

    for (int s = 0; s < T_SEQ; s++) {
        const int t = (dir == 0) ? s : (T_SEQ - 1 - s);
        const int p = s & 1;

        // ---- gate matvec: packed f32x2, row-pairs ----
        ull_t acc[RP];
        if (R == 4) {
            acc[0] = pack2(xv[0], xv[1]);
            acc[RP - 1] = pack2(xv[R - 2], xv[R - 1]);
#pragma unroll
            for (int kb = 0; kb < 32; kb++) {
                float4 w4 = Wsh4[kb * 256 + lg];
                const float* wp = (const float*)&w4;
#pragma unroll
                for (int kk = 0; kk < 4; kk++) {
                    ulonglong2 h2 = *(const ulonglong2*)&HshT[(kb * 4 + kk) * 4];
                    ull_t w2 = pack2(wp[kk], wp[kk]);
                    acc[0] = fma2(w2, h2.x, acc[0]);
                    acc[1] = fma2(w2, h2.y, acc[1]);
                }
            }
        } else {  // R == 2: two chains to cover FFMA latency, merged at end
            ull_t a0 = pack2(xv[0], xv[1]);
            ull_t a1 = pack2(0.f, 0.f);
#pragma unroll
            for (int kb = 0; kb < 32; kb++) {
                float4 w4 = Wsh4[kb * 256 + lg];
                ulonglong2 hA = *(const ulonglong2*)&HshT[(kb * 4 + 0) * 2];
                ulonglong2 hB = *(const ulonglong2*)&HshT[(kb * 4 + 2) * 2];
                a0 = fma2(pack2(w4.x, w4.x), hA.x, a0);
                a1 = fma2(pack2(w4.y, w4.y), hA.y, a1);
                a0 = fma2(pack2(w4.z, w4.z), hB.x, a0);
                a1 = fma2(pack2(w4.w, w4.w), hB.y, a1);
            }
            acc[0] = add2(a0, a1);
        }
#pragma unroll
        for (int rp = 0; rp < RP; rp++)
            *(ull_t*)&Gbuf[((p * RP + rp) * 256 + lg) * 2] = acc[rp];

        CLUSTER_ARRIVE();  // release Gbuf stores to peer; counts all CTA threads

        // prefetch xg for step s+1 while the barrier settles
        float xvn[R];
        if (s + 1 < T_SEQ) {
            const int tn = (dir == 0) ? (s + 1) : (T_SEQ - 2 - s);
#pragma unroll
            for (int r = 0; r < R; r++)
                xvn[r] = xg[((row0 + r) * T_SEQ + tn) * gst + goff + gbase + lg];
        }

        CLUSTER_WAIT();

        // ---- elementwise cell update ----
#pragma unroll
        for (int u = 0; u < R / 2; u++) {
            int rj = tid + u * 256;
            int r = rj >> 7, j = rj & 127;
            int rp = r >> 1, b = r & 1;
            int fi = ((p * RP + rp) * 256 + j) * 2 + b;   // gate lg=j
            int ff = fi + 256;                            // gate lg=128+j
            uint32_t oi = (uint32_t)fi * 4u, of = (uint32_t)ff * 4u;
            float iv, fv, gv, ov;
            if (rank == 0) {
                iv = Gbuf[fi]; fv = Gbuf[ff];
                gv = ld_cluster(gb1 + oi); ov = ld_cluster(gb1 + of);
            } else {
                gv = Gbuf[fi]; ov = Gbuf[ff];
                iv = ld_cluster(gb0 + oi); fv = ld_cluster(gb0 + of);
            }
            float cN = sigf(fv) * creg[u] + sigf(iv) * tanh_fast(gv);
            creg[u] = cN;
            float h = sigf(ov) * tanh_fast(cN);
            HshT[j * R + r] = h;
            if (rank == 0) {
                if (WRITE_ALL)
                    out[((row0 + r) * T_SEQ + t) * 256 + dir * 128 + j] = rtf32(h);
                else if (s == T_SEQ - 1)
                    out[(row0 + r) * 256 + j] = h;
            }
        }
        __syncthreads();  // HshT visible before next step's matvec
#pragma unroll
        for (int r = 0; r < R; r++) xv[r] = xvn[r];
    }
    CLUSTER_SYNC();  // don't exit while peer still reads our smem
}

// ---------------- layer1 reverse: single step with h0=0 -> pure elementwise ----------------
__global__ void l1rev_kernel() {
    int idx = blockIdx.x * blockDim.x + threadIdx.x;
    if (idx >= 128 * 128) return;
    int b = idx >> 7, j = idx & 127;
    const float* xg = g_xg1r + b * 512;
    float iv = xg[j], gv = xg[256 + j], ov = xg[384 + j];
    float c = sigf(iv) * tanh_fast(gv);
    g_h1last[b * 256 + 128 + j] = sigf(ov) * tanh_fast(c);
}

// ---------------- final FC ----------------
__global__ void fc_kernel(const float* __restrict__ fcw, const float* __restrict__ fcb,
                          float* __restrict__ out) {
    int b = blockIdx.x;
    int lane = threadIdx.x;
    float v[8];
#pragma unroll
    for (int u = 0; u < 8; u++) v[u] = g_h1last[b * 256 + lane + u * 32];
    for (int c = 0; c < 10; c++) {
        float s = 0.f;
#pragma unroll
        for (int u = 0; u < 8; u++) s = fmaf(v[u], fcw[c * 256 + lane + u * 32], s);
#pragma unroll
        for (int o = 16; o; o >>= 1) s += __shfl_xor_sync(0xffffffffu, s, o);
        if (lane == 0) out[b * 10 + c] = s + fcb[c];
    }
}

// ---------------- launch ----------------
extern "C" void kernel_launch(void* const* d_in, const int* in_sizes, int n_in,
                              void* d_out, int out_size) {
    const int*   x        = (const int*)d_in[0];
    const float* emb      = (const float*)d_in[1];
    const float* wih_l0f  = (const float*)d_in[2];
    const float* whh_l0f  = (const float*)d_in[3];
    const float* bih_l0f  = (const float*)d_in[4];
    const float* bhh_l0f  = (const float*)d_in[5];
    const float* wih_l0r  = (const float*)d_in[6];
    const float* whh_l0r  = (const float*)d_in[7];
    const float* bih_l0r  = (const float*)d_in[8];
    const float* bhh_l0r  = (const float*)d_in[9];
    const float* wih_l1f  = (const float*)d_in[10];
    const float* whh_l1f  = (const float*)d_in[11];
    const float* bih_l1f  = (const float*)d_in[12];
    const float* bhh_l1f  = (const float*)d_in[13];
    const float* wih_l1r  = (const float*)d_in[14];
    const float* bih_l1r  = (const float*)d_in[16];
    const float* bhh_l1r  = (const float*)d_in[17];
    const float* fc_w     = (const float*)d_in[18];
    const float* fc_b     = (const float*)d_in[19];
    float* out = (float*)d_out;

    float *pX0, *pWpad, *pW1, *pB0, *pB1f, *pB1r, *pXg0, *pHs0, *pXg1f, *pXg1r, *pH1;
    cudaGetSymbolAddress((void**)&pX0,   g_X0);
    cudaGetSymbolAddress((void**)&pWpad, g_Wpad);
    cudaGetSymbolAddress((void**)&pW1,   g_W1);
    cudaGetSymbolAddress((void**)&pB0,   g_bias0);
    cudaGetSymbolAddress((void**)&pB1f,  g_bias1f);
    cudaGetSymbolAddress((void**)&pB1r,  g_bias1r);
    cudaGetSymbolAddress((void**)&pXg0,  g_xg0);
    cudaGetSymbolAddress((void**)&pHs0,  g_hs0);
    cudaGetSymbolAddress((void**)&pXg1f, g_xg1f);
    cudaGetSymbolAddress((void**)&pXg1r, g_xg1r);
    cudaGetSymbolAddress((void**)&pH1,   g_h1last);

    const int SMEM_R4 = (32 * 256 * 4 + 4 * 128 + 2 * 2 * 256 * 2) * 4;   // 141312 B
    const int SMEM_R2 = (32 * 256 * 4 + 2 * 128 + 2 * 1 * 256 * 2) * 4;   // 136192 B
    cudaFuncSetAttribute(lstm_scan_kernel<4, 2, true>,
                         cudaFuncAttributeMaxDynamicSharedMemorySize, SMEM_R4);
    cudaFuncSetAttribute(lstm_scan_kernel<2, 1, false>,
                         cudaFuncAttributeMaxDynamicSharedMemorySize, SMEM_R2);

    prep_kernel<<<128, 256>>>(wih_l0f, wih_l0r, wih_l1f,
                              bih_l0f, bhh_l0f, bih_l0r, bhh_l0r,
                              bih_l1f, bhh_l1f, bih_l1r, bhh_l1r);
    embed_kernel<<<2048, 256>>>(x, emb);

    // layer 0 input gates (tensor cores via mma.sync tf32): [65536,304] x [1024,304]^T
    {
        dim3 grid(1024 / 128, MTOT / 128);
        gemm_mma_kernel<<<grid, 256>>>(pX0, KPAD, pWpad, KPAD, pXg0, 1024, KPAD, pB0);
    }
    // layer 0 scan (both dirs): 64 clusters x 2 CTAs
    lstm_scan_kernel<4, 2, true><<<128, 256, SMEM_R4>>>(pXg0, 1024, whh_l0f, whh_l0r, pHs0);

    // layer 1 forward input gates (tensor cores): [65536,256] x [512,256]^T
    {
        dim3 grid(512 / 128, MTOT / 128);
        gemm_mma_kernel<<<grid, 256>>>(pHs0, 256, pW1, 256, pXg1f, 512, 256, pB1f);
    }
    // layer 1 reverse: only t=T-1 row needed -> tiny GEMM (M=128), fp32 SIMT
    {
        dim3 grid(512 / 64, 1);
        gemm_bias_kernel<<<grid, 256>>>(pHs0 + 511 * 256, T_SEQ * 256, wih_l1r, 256,
                                        pXg1r, 512, 256, pB1r);
    }
    // layer 1 forward scan (only final h needed): 64 clusters x 2 CTAs
    lstm_scan_kernel<2, 1, false><<<128, 256, SMEM_R2>>>(pXg1f, 512, whh_l1f, whh_l1f, pH1);
    // layer 1 reverse: single step, elementwise
    l1rev_kernel<<<64, 256>>>();

    fc_kernel<<<128, 32>>>(fc_w, fc_b, out);
    (void)in_sizes; (void)n_in; (void)out_size;
}

// round 7
// speedup vs baseline: 1.8295x; 1.4301x over previous
#include <cuda_runtime.h>
#include <cstdint>

#define T_SEQ 512
#define B_SZ  128
#define HID   128
#define DEMB  300
#define KPAD  304     // padded to multiple of 16
#define MTOT  65536   // B*T

// single dynamic-smem symbol shared by all dynamic-smem kernels
extern __shared__ char k_smem[];

// ---------------- scratch (device globals; zero-init BSS) ----------------
__device__ float g_X0[MTOT * KPAD];        // padded embedded input, tf32-rounded
__device__ float g_Wpad[1024 * KPAD];      // concat(w_ih_l0f, w_ih_l0r), padded, tf32-rounded
__device__ float g_W1[512 * 256];          // w_ih_l1f, tf32-rounded
__device__ float g_bias0[1024];
__device__ float g_bias1f[512];
__device__ float g_bias1r[512];
__device__ float g_xg0[MTOT * 1024];       // layer0 input gates, both dirs
__device__ float g_hs0[MTOT * 256];        // layer0 output [b][t][fwd128|rev128] (tf32-rounded)
__device__ float g_xg1f[MTOT * 512];
__device__ float g_xg1r[128 * 512];
__device__ float g_h1last[128 * 256];      // [fwd h_T-1 | rev h_at_T-1]

// ---------------- helpers ----------------
__device__ __forceinline__ float sigf(float x) {
    return __fdividef(1.f, 1.f + __expf(-x));
}
__device__ __forceinline__ float tanh_fast(float x) {
    return 1.f - __fdividef(2.f, __expf(2.f * x) + 1.f);
}
__device__ __forceinline__ float rtf32(float x) {
    uint32_t u;
    asm("cvt.rna.tf32.f32 %0, %1;" : "=r"(u) : "f"(x));
    return __uint_as_float(u);
}
__device__ __forceinline__ uint32_t smem_u32(const void* p) {
    uint32_t a;
    asm("{ .reg .u64 t; cvta.to.shared.u64 t, %1; cvt.u32.u64 %0, t; }" : "=r"(a) : "l"(p));
    return a;
}

// ---- packed f32x2 (Blackwell base ISA; only reachable from PTX) ----
typedef unsigned long long ull_t;
__device__ __forceinline__ ull_t pack2(float x, float y) {
    ull_t r; asm("mov.b64 %0, {%1,%2};" : "=l"(r) : "f"(x), "f"(y)); return r;
}
__device__ __forceinline__ ull_t fma2(ull_t a, ull_t b, ull_t c) {
    ull_t d; asm("fma.rn.f32x2 %0, %1, %2, %3;" : "=l"(d) : "l"(a), "l"(b), "l"(c)); return d;
}
__device__ __forceinline__ ull_t add2(ull_t a, ull_t b) {
    ull_t d; asm("add.rn.f32x2 %0, %1, %2;" : "=l"(d) : "l"(a), "l"(b)); return d;
}
__device__ __forceinline__ float hadd2(ull_t a) {
    float lo, hi;
    asm("mov.b64 {%0,%1}, %2;" : "=f"(lo), "=f"(hi) : "l"(a));
    return lo + hi;
}

__device__ __forceinline__ void cp16(void* s, const void* g) {
    uint32_t sa = smem_u32(s);
    asm volatile("cp.async.cg.shared.global [%0], [%1], 16;" :: "r"(sa), "l"(g));
}
#define CP_COMMIT() asm volatile("cp.async.commit_group;" ::: "memory")
#define CP_WAIT0()  asm volatile("cp.async.wait_group 0;" ::: "memory")

__device__ __forceinline__ void mma_tf32(float* c, const uint32_t* a,
                                         uint32_t b0, uint32_t b1) {
    asm volatile(
        "mma.sync.aligned.m16n8k8.row.col.f32.tf32.tf32.f32 "
        "{%0,%1,%2,%3}, {%4,%5,%6,%7}, {%8,%9}, {%0,%1,%2,%3};"
        : "+f"(c[0]), "+f"(c[1]), "+f"(c[2]), "+f"(c[3])
        : "r"(a[0]), "r"(a[1]), "r"(a[2]), "r"(a[3]), "r"(b0), "r"(b1));
}

// ---------------- prep: pad + tf32-round weights, combine biases ----------------
__global__ void prep_kernel(const float* __restrict__ wf, const float* __restrict__ wr,
                            const float* __restrict__ w1f,
                            const float* __restrict__ bif, const float* __restrict__ bhf,
                            const float* __restrict__ bir, const float* __restrict__ bhr,
                            const float* __restrict__ b1if, const float* __restrict__ b1hf,
                            const float* __restrict__ b1ir, const float* __restrict__ b1hr) {
    int idx = blockIdx.x * blockDim.x + threadIdx.x;
    int stride = gridDim.x * blockDim.x;
    for (int i = idx; i < 1024 * KPAD; i += stride) {
        int n = i / KPAD, k = i - n * KPAD;
        float v = 0.f;
        if (k < DEMB) v = (n < 512) ? wf[n * DEMB + k] : wr[(n - 512) * DEMB + k];
        g_Wpad[i] = rtf32(v);
    }
    for (int i = idx; i < 512 * 256; i += stride) g_W1[i] = rtf32(w1f[i]);
    if (idx < 1024)
        g_bias0[idx] = (idx < 512) ? (bif[idx] + bhf[idx]) : (bir[idx - 512] + bhr[idx - 512]);
    if (idx < 512) {
        g_bias1f[idx] = b1if[idx] + b1hf[idx];
        g_bias1r[idx] = b1ir[idx] + b1hr[idx];
    }
}

// ---------------- embedding gather (tf32-rounded store) ----------------
__global__ void embed_kernel(const int* __restrict__ x, const float* __restrict__ emb) {
    int idx = blockIdx.x * blockDim.x + threadIdx.x;
    int stride = gridDim.x * blockDim.x;
    const int total = MTOT * 75;  // 75 float4 per row (300 floats); cols 300..303 stay 0
    for (int i = idx; i < total; i += stride) {
        int m = i / 75, q = i - m * 75;
        int v = x[m];
        float4 val = *(const float4*)(emb + (long)v * DEMB + q * 4);
        float4 w = make_float4(rtf32(val.x), rtf32(val.y), rtf32(val.z), rtf32(val.w));
        *(float4*)(g_X0 + (long)m * KPAD + q * 4) = w;
    }
}

// ---------------- tensor-core tf32 GEMM (base-ISA mma.sync) ----------------
#define PAD_K 20
__global__ __launch_bounds__(256) void gemm_mma_kernel(
    const float* __restrict__ A, int lda,
    const float* __restrict__ B, int ldb,
    float* __restrict__ C, int ldc,
    int K, const float* __restrict__ bias) {
    __shared__ float As[2][128 * PAD_K];
    __shared__ float Bs[2][128 * PAD_K];

    const int tid = threadIdx.x;
    const int lane = tid & 31, wid = tid >> 5;
    const int wm = wid >> 1, wn = wid & 1;        // 4 x 2 warp grid
    const int g = lane >> 2, t = lane & 3;
    const int bm = blockIdx.y * 128, bn = blockIdx.x * 128;

    float c[2][8][4];
#pragma unroll
    for (int mt = 0; mt < 2; mt++)
#pragma unroll
        for (int nt = 0; nt < 8; nt++)
#pragma unroll
            for (int j = 0; j < 4; j++) c[mt][nt][j] = 0.f;

    const int nit = K / 16;
    auto load_stage = [&](int it, int p) {
#pragma unroll
        for (int i = tid; i < 512; i += 256) {
            int r = i >> 2, q = i & 3;
            cp16(&As[p][r * PAD_K + q * 4], A + (long)(bm + r) * lda + it * 16 + q * 4);
        }
#pragma unroll
        for (int i = tid; i < 512; i += 256) {
            int r = i >> 2, q = i & 3;
            cp16(&Bs[p][r * PAD_K + q * 4], B + (long)(bn + r) * ldb + it * 16 + q * 4);
        }
        CP_COMMIT();
    };

    load_stage(0, 0);
    for (int it = 0; it < nit; it++) {
        CP_WAIT0();
        __syncthreads();
        if (it + 1 < nit) load_stage(it + 1, (it + 1) & 1);
        const int p = it & 1;
        const float* Ab = As[p] + (wm * 32) * PAD_K;
        const float* Bb = Bs[p] + (wn * 64) * PAD_K;
#pragma unroll
        for (int ks = 0; ks < 2; ks++) {
            const int k0 = ks * 8;
            uint32_t afr[2][4];
#pragma unroll
            for (int mt = 0; mt < 2; mt++) {
                const float* r0 = Ab + (mt * 16 + g) * PAD_K + k0 + t;
                const float* r1 = r0 + 8 * PAD_K;
                afr[mt][0] = __float_as_uint(r0[0]);
                afr[mt][1] = __float_as_uint(r1[0]);
                afr[mt][2] = __float_as_uint(r0[4]);
                afr[mt][3] = __float_as_uint(r1[4]);
            }
#pragma unroll
            for (int nt = 0; nt < 8; nt++) {
                const float* br = Bb + (nt * 8 + g) * PAD_K + k0 + t;
                uint32_t b0 = __float_as_uint(br[0]);
                uint32_t b1 = __float_as_uint(br[4]);
                mma_tf32(c[0][nt], afr[0], b0, b1);
                mma_tf32(c[1][nt], afr[1], b0, b1);
            }
        }
        __syncthreads();
    }

#pragma unroll
    for (int mt = 0; mt < 2; mt++) {
        const int row = bm + wm * 32 + mt * 16 + g;
#pragma unroll
        for (int nt = 0; nt < 8; nt++) {
            const int col = bn + wn * 64 + nt * 8 + 2 * t;
            float2 bb = *(const float2*)(bias + col);
            float2 o0 = make_float2(c[mt][nt][0] + bb.x, c[mt][nt][1] + bb.y);
            float2 o1 = make_float2(c[mt][nt][2] + bb.x, c[mt][nt][3] + bb.y);
            *(float2*)(C + (long)row * ldc + col) = o0;
            *(float2*)(C + (long)(row + 8) * ldc + col) = o1;
        }
    }
}

// ---------------- fp32 tiled GEMM (tiny layer-1 reverse GEMM only) ----------------
__global__ __launch_bounds__(256) void gemm_bias_kernel(
    const float* __restrict__ A, int lda,
    const float* __restrict__ B, int ldb,
    float* __restrict__ C, int ldc,
    int K, const float* __restrict__ bias) {
    __shared__ float As[16][132];
    __shared__ float Bs[16][68];

    const int tid = threadIdx.x;
    const int bm = blockIdx.y * 128, bn = blockIdx.x * 64;
    const int tx = tid & 15, ty = tid >> 4;
    const int arow = tid >> 2, acol = tid & 3;

    float acc[8][4];
#pragma unroll
    for (int i = 0; i < 8; i++)
#pragma unroll
        for (int j = 0; j < 4; j++) acc[i][j] = 0.f;

    const float* Aptr = A + (long)(bm + arow) * lda + acol * 4;
    const float* Bptr = B + (long)(bn + arow) * ldb + acol * 4;

    for (int k0 = 0; k0 < K; k0 += 16) {
        float4 a0 = *(const float4*)(Aptr + k0);
        float4 a1 = *(const float4*)(Aptr + (long)64 * lda + k0);
        float4 b0 = *(const float4*)(Bptr + k0);
        __syncthreads();
        As[acol * 4 + 0][arow] = a0.x; As[acol * 4 + 1][arow] = a0.y;
        As[acol * 4 + 2][arow] = a0.z; As[acol * 4 + 3][arow] = a0.w;
        As[acol * 4 + 0][arow + 64] = a1.x; As[acol * 4 + 1][arow + 64] = a1.y;
        As[acol * 4 + 2][arow + 64] = a1.z; As[acol * 4 + 3][arow + 64] = a1.w;
        Bs[acol * 4 + 0][arow] = b0.x; Bs[acol * 4 + 1][arow] = b0.y;
        Bs[acol * 4 + 2][arow] = b0.z; Bs[acol * 4 + 3][arow] = b0.w;
        __syncthreads();
#pragma unroll
        for (int k = 0; k < 16; k++) {
            float4 av0 = *(float4*)&As[k][ty * 8];
            float4 av1 = *(float4*)&As[k][ty * 8 + 4];
            float4 bv  = *(float4*)&Bs[k][tx * 4];
            float a[8] = {av0.x, av0.y, av0.z, av0.w, av1.x, av1.y, av1.z, av1.w};
            float b[4] = {bv.x, bv.y, bv.z, bv.w};
#pragma unroll
            for (int i = 0; i < 8; i++)
#pragma unroll
                for (int j = 0; j < 4; j++) acc[i][j] = fmaf(a[i], b[j], acc[i][j]);
        }
    }
    float4 bb = *(const float4*)(bias + bn + tx * 4);
#pragma unroll
    for (int i = 0; i < 8; i++) {
        float4 o;
        o.x = acc[i][0] + bb.x; o.y = acc[i][1] + bb.y;
        o.z = acc[i][2] + bb.z; o.w = acc[i][3] + bb.w;
        *(float4*)(C + (long)(bm + ty * 8 + i) * ldc + bn + tx * 4) = o;
    }
}

// ---------------- LSTM recurrence: single-CTA, 512 threads, reg+smem weights ----------------
// One CTA per (direction, batch-chunk of R rows). Thread tid owns gate tid (of 512).
// Weight row 128-wide: k=0..63 in 32 f32x2 registers, k=64..127 in smem
// ([q][gate] pair layout, conflict-free). Gates exchanged via smem + __syncthreads.
template <int R, int NDIR, bool WRITE_ALL>
__global__ __launch_bounds__(512, 1)
void lstm_scan2_kernel(const float* __restrict__ xg, int gst,
                       const float* __restrict__ whh_f, const float* __restrict__ whh_r,
                       float* __restrict__ out) {
    float* smem = (float*)k_smem;
    ull_t* WshS = (ull_t*)smem;            // [16][512][2] ull = 128KB (k=64..127)
    float* Hsh  = smem + 32768;            // [R][128]
    float* Gbuf = Hsh + R * 128;           // [R][512]

    const int tid = threadIdx.x;
    int dir, chunk;
    if (NDIR == 2) { dir = blockIdx.x & 1; chunk = blockIdx.x >> 1; }
    else           { dir = 0;              chunk = blockIdx.x; }
    const int row0 = chunk * R;
    const float* whh = (dir == 0) ? whh_f : whh_r;
    const int goff = (NDIR == 2) ? dir * 512 : 0;
    const int lg = tid;

    // load weights: k=0..63 -> registers, k=64..127 -> smem
    ull_t wreg[32];
    {
        const float* wrow = whh + lg * 128;
#pragma unroll
        for (int q = 0; q < 16; q++) {
            float4 v = *(const float4*)(wrow + q * 4);
            wreg[2 * q]     = pack2(v.x, v.y);
            wreg[2 * q + 1] = pack2(v.z, v.w);
        }
#pragma unroll
        for (int q = 0; q < 16; q++) {
            float4 v = *(const float4*)(wrow + 64 + q * 4);
            WshS[q * 1024 + lg * 2 + 0] = pack2(v.x, v.y);
            WshS[q * 1024 + lg * 2 + 1] = pack2(v.z, v.w);
        }
    }
    for (int i = tid; i < R * 128; i += 512) Hsh[i] = 0.f;
    __syncthreads();

    float creg = 0.f;  // cell state: owned by threads tid < 128*R (one (r,j) each)

    // preload xg for step 0
    float xv[R];
    {
        const int t0 = (dir == 0) ? 0 : (T_SEQ - 1);
#pragma unroll
        for (int r = 0; r < R; r++)
            xv[r] = xg[((row0 + r) * T_SEQ + t0) * gst + goff + lg];
    }

    for (int s = 0; s < T_SEQ; s++) {
        const int t = (dir == 0) ? s : (T_SEQ - 1 - s);

        // ---- gate matvec: 2 accumulator chains per row (cover FFMA latency) ----
        ull_t accA[R], accB[R];
#pragma unroll
        for (int r = 0; r < R; r++) {
            accA[r] = pack2(xv[r], 0.f);
            accB[r] = pack2(0.f, 0.f);
        }
#pragma unroll
        for (int q = 0; q < 16; q++) {
#pragma unroll
            for (int r = 0; r < R; r++) {
                ulonglong2 h2 = *(const ulonglong2*)&Hsh[r * 128 + q * 4];
                accA[r] = fma2(wreg[2 * q], h2.x, accA[r]);
                accB[r] = fma2(wreg[2 * q + 1], h2.y, accB[r]);
            }
        }
#pragma unroll
        for (int q = 0; q < 16; q++) {
            ulonglong2 w2 = *(const ulonglong2*)(WshS + q * 1024 + lg * 2);
#pragma unroll
            for (int r = 0; r < R; r++) {
                ulonglong2 h2 = *(const ulonglong2*)&Hsh[r * 128 + 64 + q * 4];
                accA[r] = fma2(w2.x, h2.x, accA[r]);
                accB[r] = fma2(w2.y, h2.y, accB[r]);
            }
        }
#pragma unroll
        for (int r = 0; r < R; r++)
            Gbuf[r * 512 + lg] = hadd2(add2(accA[r], accB[r]));

        // prefetch next xg while stores settle
        float xvn[R];
        if (s + 1 < T_SEQ) {
            const int tn = (dir == 0) ? (s + 1) : (T_SEQ - 2 - s);
#pragma unroll
            for (int r = 0; r < R; r++)
                xvn[r] = xg[((row0 + r) * T_SEQ + tn) * gst + goff + lg];
        }
        __syncthreads();

        // ---- elementwise cell update: threads 0..128*R-1 ----
        if (tid < 128 * R) {
            const int r = tid >> 7, j = tid & 127;
            const float* gb = Gbuf + r * 512;
            float iv = gb[j], fv = gb[128 + j], gv = gb[256 + j], ov = gb[384 + j];
            float cN = sigf(fv) * creg + sigf(iv) * tanh_fast(gv);
            creg = cN;
            float h = sigf(ov) * tanh_fast(cN);
            Hsh[r * 128 + j] = h;
            if (WRITE_ALL)
                out[((row0 + r) * T_SEQ + t) * 256 + dir * 128 + j] = rtf32(h);
            else if (s == T_SEQ - 1)
                out[(row0 + r) * 256 + j] = h;
        }
        __syncthreads();
#pragma unroll
        for (int r = 0; r < R; r++) xv[r] = xvn[r];
    }
}

// ---------------- layer1 reverse: single step with h0=0 -> pure elementwise ----------------
__global__ void l1rev_kernel() {
    int idx = blockIdx.x * blockDim.x + threadIdx.x;
    if (idx >= 128 * 128) return;
    int b = idx >> 7, j = idx & 127;
    const float* xg = g_xg1r + b * 512;
    float iv = xg[j], gv = xg[256 + j], ov = xg[384 + j];
    float c = sigf(iv) * tanh_fast(gv);
    g_h1last[b * 256 + 128 + j] = sigf(ov) * tanh_fast(c);
}

// ---------------- final FC ----------------
__global__ void fc_kernel(const float* __restrict__ fcw, const float* __restrict__ fcb,
                          float* __restrict__ out) {
    int b = blockIdx.x;
    int lane = threadIdx.x;
    float v[8];
#pragma unroll
    for (int u = 0; u < 8; u++) v[u] = g_h1last[b * 256 + lane + u * 32];
    for (int c = 0; c < 10; c++) {
        float s = 0.f;
#pragma unroll
        for (int u = 0; u < 8; u++) s = fmaf(v[u], fcw[c * 256 + lane + u * 32], s);
#pragma unroll
        for (int o = 16; o; o >>= 1) s += __shfl_xor_sync(0xffffffffu, s, o);
        if (lane == 0) out[b * 10 + c] = s + fcb[c];
    }
}

// ---------------- launch ----------------
extern "C" void kernel_launch(void* const* d_in, const int* in_sizes, int n_in,
                              void* d_out, int out_size) {
    const int*   x        = (const int*)d_in[0];
    const float* emb      = (const float*)d_in[1];
    const float* wih_l0f  = (const float*)d_in[2];
    const float* whh_l0f  = (const float*)d_in[3];
    const float* bih_l0f  = (const float*)d_in[4];
    const float* bhh_l0f  = (const float*)d_in[5];
    const float* wih_l0r  = (const float*)d_in[6];
    const float* whh_l0r  = (const float*)d_in[7];
    const float* bih_l0r  = (const float*)d_in[8];
    const float* bhh_l0r  = (const float*)d_in[9];
    const float* wih_l1f  = (const float*)d_in[10];
    const float* whh_l1f  = (const float*)d_in[11];
    const float* bih_l1f  = (const float*)d_in[12];
    const float* bhh_l1f  = (const float*)d_in[13];
    const float* wih_l1r  = (const float*)d_in[14];
    const float* bih_l1r  = (const float*)d_in[16];
    const float* bhh_l1r  = (const float*)d_in[17];
    const float* fc_w     = (const float*)d_in[18];
    const float* fc_b     = (const float*)d_in[19];
    float* out = (float*)d_out;

    float *pX0, *pWpad, *pW1, *pB0, *pB1f, *pB1r, *pXg0, *pHs0, *pXg1f, *pXg1r, *pH1;
    cudaGetSymbolAddress((void**)&pX0,   g_X0);
    cudaGetSymbolAddress((void**)&pWpad, g_Wpad);
    cudaGetSymbolAddress((void**)&pW1,   g_W1);
    cudaGetSymbolAddress((void**)&pB0,   g_bias0);
    cudaGetSymbolAddress((void**)&pB1f,  g_bias1f);
    cudaGetSymbolAddress((void**)&pB1r,  g_bias1r);
    cudaGetSymbolAddress((void**)&pXg0,  g_xg0);
    cudaGetSymbolAddress((void**)&pHs0,  g_hs0);
    cudaGetSymbolAddress((void**)&pXg1f, g_xg1f);
    cudaGetSymbolAddress((void**)&pXg1r, g_xg1r);
    cudaGetSymbolAddress((void**)&pH1,   g_h1last);

    const int SMEM_S2 = 131072 + (2 * 128 + 2 * 512) * 4;   // 136192 B (R=2)
    const int SMEM_S1 = 131072 + (1 * 128 + 1 * 512) * 4;   // 133632 B (R=1)
    cudaFuncSetAttribute(lstm_scan2_kernel<2, 2, true>,
                         cudaFuncAttributeMaxDynamicSharedMemorySize, SMEM_S2);
    cudaFuncSetAttribute(lstm_scan2_kernel<1, 1, false>,
                         cudaFuncAttributeMaxDynamicSharedMemorySize, SMEM_S1);

    prep_kernel<<<128, 256>>>(wih_l0f, wih_l0r, wih_l1f,
                              bih_l0f, bhh_l0f, bih_l0r, bhh_l0r,
                              bih_l1f, bhh_l1f, bih_l1r, bhh_l1r);
    embed_kernel<<<2048, 256>>>(x, emb);

    // layer 0 input gates (tensor cores via mma.sync tf32): [65536,304] x [1024,304]^T
    {
        dim3 grid(1024 / 128, MTOT / 128);
        gemm_mma_kernel<<<grid, 256>>>(pX0, KPAD, pWpad, KPAD, pXg0, 1024, KPAD, pB0);
    }
    // layer 0 scan (both dirs): 128 single CTAs (2 dirs x 64 chunks, R=2)
    lstm_scan2_kernel<2, 2, true><<<128, 512, SMEM_S2>>>(pXg0, 1024, whh_l0f, whh_l0r, pHs0);

    // layer 1 forward input gates (tensor cores): [65536,256] x [512,256]^T
    {
        dim3 grid(512 / 128, MTOT / 128);
        gemm_mma_kernel<<<grid, 256>>>(pHs0, 256, pW1, 256, pXg1f, 512, 256, pB1f);
    }
    // layer 1 reverse: only t=T-1 row needed -> tiny GEMM (M=128), fp32 SIMT
    {
        dim3 grid(512 / 64, 1);
        gemm_bias_kernel<<<grid, 256>>>(pHs0 + 511 * 256, T_SEQ * 256, wih_l1r, 256,
                                        pXg1r, 512, 256, pB1r);
    }
    // layer 1 forward scan (only final h needed): 128 single CTAs (R=1)
    lstm_scan2_kernel<1, 1, false><<<128, 512, SMEM_S1>>>(pXg1f, 512, whh_l1f, whh_l1f, pH1);
    // layer 1 reverse: single step, elementwise
    l1rev_kernel<<<64, 256>>>();

    fc_kernel<<<128, 32>>>(fc_w, fc_b, out);
    (void)in_sizes; (void)n_in; (void)out_size;
}

// round 8
// speedup vs baseline: 2.0543x; 1.1229x over previous
#include <cuda_runtime.h>
#include <cuda_fp16.h>
#include <cstdint>

#define T_SEQ 512
#define B_SZ  128
#define HID   128
#define DEMB  300
#define KPAD  304     // padded to multiple of 16
#define MTOT  65536   // B*T

// single dynamic-smem symbol shared by all dynamic-smem kernels
extern __shared__ char k_smem[];

// ---------------- scratch (device globals; zero-init BSS) ----------------
__device__ float g_X0[MTOT * KPAD];        // padded embedded input, tf32-rounded
__device__ float g_Wpad[1024 * KPAD];      // concat(w_ih_l0f, w_ih_l0r), padded, tf32-rounded
__device__ float g_W1[512 * 256];          // w_ih_l1f, tf32-rounded
__device__ float g_bias0[1024];
__device__ float g_bias1f[512];
__device__ float g_bias1r[512];
__device__ float g_xg0[MTOT * 1024];       // layer0 input gates, both dirs
__device__ float g_hs0[MTOT * 256];        // layer0 output [b][t][fwd128|rev128] (tf32-rounded)
__device__ float g_xg1f[MTOT * 512];
__device__ float g_xg1r[128 * 512];
__device__ float g_h1last[128 * 256];      // [fwd h_T-1 | rev h_at_T-1]

// ---------------- helpers ----------------
__device__ __forceinline__ float sigf(float x) {
    return __fdividef(1.f, 1.f + __expf(-x));
}
__device__ __forceinline__ float tanh_fast(float x) {
    return 1.f - __fdividef(2.f, __expf(2.f * x) + 1.f);
}
__device__ __forceinline__ float rtf32(float x) {
    uint32_t u;
    asm("cvt.rna.tf32.f32 %0, %1;" : "=r"(u) : "f"(x));
    return __uint_as_float(u);
}
__device__ __forceinline__ float rcpf(float x) {
    float r; asm("rcp.approx.ftz.f32 %0, %1;" : "=f"(r) : "f"(x)); return r;
}
__device__ __forceinline__ uint32_t smem_u32(const void* p) {
    uint32_t a;
    asm("{ .reg .u64 t; cvta.to.shared.u64 t, %1; cvt.u32.u64 %0, t; }" : "=r"(a) : "l"(p));
    return a;
}
__device__ __forceinline__ uint32_t f2h2(float x, float y) {
    __half2 h = __floats2half2_rn(x, y);
    return *reinterpret_cast<uint32_t*>(&h);
}

__device__ __forceinline__ void cp16(void* s, const void* g) {
    uint32_t sa = smem_u32(s);
    asm volatile("cp.async.cg.shared.global [%0], [%1], 16;" :: "r"(sa), "l"(g));
}
#define CP_COMMIT() asm volatile("cp.async.commit_group;" ::: "memory")
#define CP_WAIT0()  asm volatile("cp.async.wait_group 0;" ::: "memory")

__device__ __forceinline__ void mma_tf32(float* c, const uint32_t* a,
                                         uint32_t b0, uint32_t b1) {
    asm volatile(
        "mma.sync.aligned.m16n8k8.row.col.f32.tf32.tf32.f32 "
        "{%0,%1,%2,%3}, {%4,%5,%6,%7}, {%8,%9}, {%0,%1,%2,%3};"
        : "+f"(c[0]), "+f"(c[1]), "+f"(c[2]), "+f"(c[3])
        : "r"(a[0]), "r"(a[1]), "r"(a[2]), "r"(a[3]), "r"(b0), "r"(b1));
}

__device__ __forceinline__ void mma_f16(float& c0, float& c1, float& c2, float& c3,
                                        uint32_t a0, uint32_t a1, uint32_t a2, uint32_t a3,
                                        uint32_t b0, uint32_t b1) {
    asm volatile(
        "mma.sync.aligned.m16n8k16.row.col.f32.f16.f16.f32 "
        "{%0,%1,%2,%3}, {%4,%5,%6,%7}, {%8,%9}, {%0,%1,%2,%3};"
        : "+f"(c0), "+f"(c1), "+f"(c2), "+f"(c3)
        : "r"(a0), "r"(a1), "r"(a2), "r"(a3), "r"(b0), "r"(b1));
}

// LSTM cell: c' = sig(f)c + sig(i)tanh(g); h = sig(o)tanh(c').
// Common-denominator form: 7 MUFU (5 EX2 + 2 RCP). Gates clamped to +-15 so
// denominator products stay finite (max ~e^60 < fp32 max).
__device__ __forceinline__ void lstm_cell(float gi, float gf, float gg, float go,
                                          float& c, float& h) {
    gi = fminf(fmaxf(gi, -15.f), 15.f);
    gf = fminf(fmaxf(gf, -15.f), 15.f);
    gg = fminf(fmaxf(gg, -15.f), 15.f);
    go = fminf(fmaxf(go, -15.f), 15.f);
    float ei = __expf(-gi), ef = __expf(-gf), eg = __expf(-2.f * gg);
    float pi = 1.f + ei, pf = 1.f + ef, pg = 1.f + eg;
    float num = c * (pi * pg) + pf * (1.f - eg);
    float cN = num * rcpf(pf * pi * pg);
    c = cN;
    float ch = fminf(fmaxf(cN, -15.f), 15.f);
    float eo = __expf(-go), ec = __expf(-2.f * ch);
    h = (1.f - ec) * rcpf((1.f + eo) * (1.f + ec));
}

// ---------------- prep: pad + tf32-round weights, combine biases ----------------
__global__ void prep_kernel(const float* __restrict__ wf, const float* __restrict__ wr,
                            const float* __restrict__ w1f,
                            const float* __restrict__ bif, const float* __restrict__ bhf,
                            const float* __restrict__ bir, const float* __restrict__ bhr,
                            const float* __restrict__ b1if, const float* __restrict__ b1hf,
                            const float* __restrict__ b1ir, const float* __restrict__ b1hr) {
    int idx = blockIdx.x * blockDim.x + threadIdx.x;
    int stride = gridDim.x * blockDim.x;
    for (int i = idx; i < 1024 * KPAD; i += stride) {
        int n = i / KPAD, k = i - n * KPAD;
        float v = 0.f;
        if (k < DEMB) v = (n < 512) ? wf[n * DEMB + k] : wr[(n - 512) * DEMB + k];
        g_Wpad[i] = rtf32(v);
    }
    for (int i = idx; i < 512 * 256; i += stride) g_W1[i] = rtf32(w1f[i]);
    if (idx < 1024)
        g_bias0[idx] = (idx < 512) ? (bif[idx] + bhf[idx]) : (bir[idx - 512] + bhr[idx - 512]);
    if (idx < 512) {
        g_bias1f[idx] = b1if[idx] + b1hf[idx];
        g_bias1r[idx] = b1ir[idx] + b1hr[idx];
    }
}

// ---------------- embedding gather (tf32-rounded store) ----------------
__global__ void embed_kernel(const int* __restrict__ x, const float* __restrict__ emb) {
    int idx = blockIdx.x * blockDim.x + threadIdx.x;
    int stride = gridDim.x * blockDim.x;
    const int total = MTOT * 75;  // 75 float4 per row (300 floats); cols 300..303 stay 0
    for (int i = idx; i < total; i += stride) {
        int m = i / 75, q = i - m * 75;
        int v = x[m];
        float4 val = *(const float4*)(emb + (long)v * DEMB + q * 4);
        float4 w = make_float4(rtf32(val.x), rtf32(val.y), rtf32(val.z), rtf32(val.w));
        *(float4*)(g_X0 + (long)m * KPAD + q * 4) = w;
    }
}

// ---------------- tensor-core tf32 GEMM (base-ISA mma.sync) ----------------
#define PAD_K 20
__global__ __launch_bounds__(256) void gemm_mma_kernel(
    const float* __restrict__ A, int lda,
    const float* __restrict__ B, int ldb,
    float* __restrict__ C, int ldc,
    int K, const float* __restrict__ bias) {
    __shared__ float As[2][128 * PAD_K];
    __shared__ float Bs[2][128 * PAD_K];

    const int tid = threadIdx.x;
    const int lane = tid & 31, wid = tid >> 5;
    const int wm = wid >> 1, wn = wid & 1;        // 4 x 2 warp grid
    const int g = lane >> 2, t = lane & 3;
    const int bm = blockIdx.y * 128, bn = blockIdx.x * 128;

    float c[2][8][4];
#pragma unroll
    for (int mt = 0; mt < 2; mt++)
#pragma unroll
        for (int nt = 0; nt < 8; nt++)
#pragma unroll
            for (int j = 0; j < 4; j++) c[mt][nt][j] = 0.f;

    const int nit = K / 16;
    auto load_stage = [&](int it, int p) {
#pragma unroll
        for (int i = tid; i < 512; i += 256) {
            int r = i >> 2, q = i & 3;
            cp16(&As[p][r * PAD_K + q * 4], A + (long)(bm + r) * lda + it * 16 + q * 4);
        }
#pragma unroll
        for (int i = tid; i < 512; i += 256) {
            int r = i >> 2, q = i & 3;
            cp16(&Bs[p][r * PAD_K + q * 4], B + (long)(bn + r) * ldb + it * 16 + q * 4);
        }
        CP_COMMIT();
    };

    load_stage(0, 0);
    for (int it = 0; it < nit; it++) {
        CP_WAIT0();
        __syncthreads();
        if (it + 1 < nit) load_stage(it + 1, (it + 1) & 1);
        const int p = it & 1;
        const float* Ab = As[p] + (wm * 32) * PAD_K;
        const float* Bb = Bs[p] + (wn * 64) * PAD_K;
#pragma unroll
        for (int ks = 0; ks < 2; ks++) {
            const int k0 = ks * 8;
            uint32_t afr[2][4];
#pragma unroll
            for (int mt = 0; mt < 2; mt++) {
                const float* r0 = Ab + (mt * 16 + g) * PAD_K + k0 + t;
                const float* r1 = r0 + 8 * PAD_K;
                afr[mt][0] = __float_as_uint(r0[0]);
                afr[mt][1] = __float_as_uint(r1[0]);
                afr[mt][2] = __float_as_uint(r0[4]);
                afr[mt][3] = __float_as_uint(r1[4]);
            }
#pragma unroll
            for (int nt = 0; nt < 8; nt++) {
                const float* br = Bb + (nt * 8 + g) * PAD_K + k0 + t;
                uint32_t b0 = __float_as_uint(br[0]);
                uint32_t b1 = __float_as_uint(br[4]);
                mma_tf32(c[0][nt], afr[0], b0, b1);
                mma_tf32(c[1][nt], afr[1], b0, b1);
            }
        }
        __syncthreads();
    }

#pragma unroll
    for (int mt = 0; mt < 2; mt++) {
        const int row = bm + wm * 32 + mt * 16 + g;
#pragma unroll
        for (int nt = 0; nt < 8; nt++) {
            const int col = bn + wn * 64 + nt * 8 + 2 * t;
            float2 bb = *(const float2*)(bias + col);
            float2 o0 = make_float2(c[mt][nt][0] + bb.x, c[mt][nt][1] + bb.y);
            float2 o1 = make_float2(c[mt][nt][2] + bb.x, c[mt][nt][3] + bb.y);
            *(float2*)(C + (long)row * ldc + col) = o0;
            *(float2*)(C + (long)(row + 8) * ldc + col) = o1;
        }
    }
}

// ---------------- fp32 tiled GEMM (tiny layer-1 reverse GEMM only) ----------------
__global__ __launch_bounds__(256) void gemm_bias_kernel(
    const float* __restrict__ A, int lda,
    const float* __restrict__ B, int ldb,
    float* __restrict__ C, int ldc,
    int K, const float* __restrict__ bias) {
    __shared__ float As[16][132];
    __shared__ float Bs[16][68];

    const int tid = threadIdx.x;
    const int bm = blockIdx.y * 128, bn = blockIdx.x * 64;
    const int tx = tid & 15, ty = tid >> 4;
    const int arow = tid >> 2, acol = tid & 3;

    float acc[8][4];
#pragma unroll
    for (int i = 0; i < 8; i++)
#pragma unroll
        for (int j = 0; j < 4; j++) acc[i][j] = 0.f;

    const float* Aptr = A + (long)(bm + arow) * lda + acol * 4;
    const float* Bptr = B + (long)(bn + arow) * ldb + acol * 4;

    for (int k0 = 0; k0 < K; k0 += 16) {
        float4 a0 = *(const float4*)(Aptr + k0);
        float4 a1 = *(const float4*)(Aptr + (long)64 * lda + k0);
        float4 b0 = *(const float4*)(Bptr + k0);
        __syncthreads();
        As[acol * 4 + 0][arow] = a0.x; As[acol * 4 + 1][arow] = a0.y;
        As[acol * 4 + 2][arow] = a0.z; As[acol * 4 + 3][arow] = a0.w;
        As[acol * 4 + 0][arow + 64] = a1.x; As[acol * 4 + 1][arow + 64] = a1.y;
        As[acol * 4 + 2][arow + 64] = a1.z; As[acol * 4 + 3][arow + 64] = a1.w;
        Bs[acol * 4 + 0][arow] = b0.x; Bs[acol * 4 + 1][arow] = b0.y;
        Bs[acol * 4 + 2][arow] = b0.z; Bs[acol * 4 + 3][arow] = b0.w;
        __syncthreads();
#pragma unroll
        for (int k = 0; k < 16; k++) {
            float4 av0 = *(float4*)&As[k][ty * 8];
            float4 av1 = *(float4*)&As[k][ty * 8 + 4];
            float4 bv  = *(float4*)&Bs[k][tx * 4];
            float a[8] = {av0.x, av0.y, av0.z, av0.w, av1.x, av1.y, av1.z, av1.w};
            float b[4] = {bv.x, bv.y, bv.z, bv.w};
#pragma unroll
            for (int i = 0; i < 8; i++)
#pragma unroll
                for (int j = 0; j < 4; j++) acc[i][j] = fmaf(a[i], b[j], acc[i][j]);
        }
    }
    float4 bb = *(const float4*)(bias + bn + tx * 4);
#pragma unroll
    for (int i = 0; i < 8; i++) {
        float4 o;
        o.x = acc[i][0] + bb.x; o.y = acc[i][1] + bb.y;
        o.z = acc[i][2] + bb.z; o.w = acc[i][3] + bb.w;
        *(float4*)(C + (long)(bm + ty * 8 + i) * ldc + bn + tx * 4) = o;
    }
}

// ---------------- LSTM recurrence: m16n8k16 fp16 MMA, 8 batch rows per CTA ----------------
// 512 threads = 16 warps. Warp w computes gates [w*32, w*32+32) (nt=4 n-tiles) for
// all 8 batch rows via mma with register-resident fp16 w_hh fragments (A rows 8..15
// are zero). H lives in smem as fp16x2 in fragment-addressable layout; gates routed
// through padded smem Gbuf; elementwise spread over all 512 lanes (2 cells each).
#define MR 8
#define HP 68    // Hsh2 row stride (fp16x2 words)
#define GP 520   // Gbuf row stride (floats)
template <int NDIR, bool WRITE_ALL>
__global__ __launch_bounds__(512, 1)
void lstm_mma_kernel(const float* __restrict__ xg, int gst,
                     const float* __restrict__ whh_f, const float* __restrict__ whh_r,
                     float* __restrict__ out) {
    float* smem = (float*)k_smem;
    uint32_t* Hsh2 = (uint32_t*)smem;         // [8][HP] fp16x2 pairs of h
    float* Gbuf = smem + MR * HP;             // [8][GP] gates fp32

    const int tid = threadIdx.x;
    const int lane = tid & 31, w = tid >> 5;
    const int gq = lane >> 2, c4 = lane & 3;  // lane/4, lane%4
    int dir, chunk;
    if (NDIR == 2) { dir = blockIdx.x & 1; chunk = blockIdx.x >> 1; }
    else           { dir = 0;              chunk = blockIdx.x; }
    const int row0 = chunk * MR;
    const float* whh = (dir == 0) ? whh_f : whh_r;
    const int goff = (NDIR == 2) ? dir * 512 : 0;

    // ---- pack w_hh B-fragments into registers (fp16), once ----
    uint32_t bfrag[4][8][2];
#pragma unroll
    for (int nt = 0; nt < 4; nt++) {
        const int n = w * 32 + nt * 8 + gq;
        const float* wp = whh + n * 128;
#pragma unroll
        for (int kt = 0; kt < 8; kt++) {
            float2 v0 = *(const float2*)(wp + kt * 16 + 2 * c4);
            float2 v1 = *(const float2*)(wp + kt * 16 + 2 * c4 + 8);
            bfrag[nt][kt][0] = f2h2(v0.x, v0.y);
            bfrag[nt][kt][1] = f2h2(v1.x, v1.y);
        }
    }
    for (int i = tid; i < MR * HP; i += 512) Hsh2[i] = 0;
    __syncthreads();

    // elementwise ownership: thread -> (m = tid/64, j0 = 2*(tid%64), j0+1)
    const int em = tid >> 6;
    const int eq = tid & 63;
    float cr0 = 0.f, cr1 = 0.f;
    const float* xrow = xg + (long)(row0 + em) * T_SEQ * gst + goff + 2 * eq;

    float2 xi, xf, xgv, xo;
    {
        const int t0 = (dir == 0) ? 0 : (T_SEQ - 1);
        const float* b = xrow + (long)t0 * gst;
        xi = *(const float2*)(b);       xf = *(const float2*)(b + 128);
        xgv = *(const float2*)(b + 256); xo = *(const float2*)(b + 384);
    }

    for (int s = 0; s < T_SEQ; s++) {
        const int t = (dir == 0) ? s : (T_SEQ - 1 - s);

        // ---- gate MMA: G[8,512] = H[8,128] @ Whh^T ----
        float cf[4][2];
#pragma unroll
        for (int nt = 0; nt < 4; nt++) { cf[nt][0] = 0.f; cf[nt][1] = 0.f; }
        float dz0 = 0.f, dz1 = 0.f;  // rows 8..15 sinks (stay 0: a1=a3=0)
#pragma unroll
        for (int kt = 0; kt < 8; kt++) {
            uint32_t a0 = Hsh2[gq * HP + kt * 8 + c4];
            uint32_t a2 = Hsh2[gq * HP + kt * 8 + c4 + 4];
#pragma unroll
            for (int nt = 0; nt < 4; nt++)
                mma_f16(cf[nt][0], cf[nt][1], dz0, dz1,
                        a0, 0u, a2, 0u, bfrag[nt][kt][0], bfrag[nt][kt][1]);
        }
#pragma unroll
        for (int nt = 0; nt < 4; nt++)
            *(float2*)&Gbuf[gq * GP + w * 32 + nt * 8 + 2 * c4] =
                make_float2(cf[nt][0], cf[nt][1]);

        // prefetch next-step xg while gate stores settle
        float2 ni, nf, ng, no;
        if (s + 1 < T_SEQ) {
            const int tn = (dir == 0) ? (s + 1) : (T_SEQ - 2 - s);
            const float* b = xrow + (long)tn * gst;
            ni = *(const float2*)(b);       nf = *(const float2*)(b + 128);
            ng = *(const float2*)(b + 256); no = *(const float2*)(b + 384);
        }
        __syncthreads();

        // ---- elementwise: 2 cells per thread ----
        {
            const float* gb = Gbuf + em * GP + 2 * eq;
            float2 gi = *(const float2*)(gb);
            float2 gf = *(const float2*)(gb + 128);
            float2 gg = *(const float2*)(gb + 256);
            float2 go = *(const float2*)(gb + 384);
            float h0, h1;
            lstm_cell(gi.x + xi.x, gf.x + xf.x, gg.x + xgv.x, go.x + xo.x, cr0, h0);
            lstm_cell(gi.y + xi.y, gf.y + xf.y, gg.y + xgv.y, go.y + xo.y, cr1, h1);
            Hsh2[em * HP + eq] = f2h2(h0, h1);
            if (WRITE_ALL) {
                *(float2*)&out[((long)(row0 + em) * T_SEQ + t) * 256 + dir * 128 + 2 * eq] =
                    make_float2(rtf32(h0), rtf32(h1));
            } else if (s == T_SEQ - 1) {
                *(float2*)&out[(row0 + em) * 256 + 2 * eq] = make_float2(h0, h1);
            }
        }
        __syncthreads();
        xi = ni; xf = nf; xgv = ng; xo = no;
    }
}

// ---------------- layer1 reverse: single step with h0=0 -> pure elementwise ----------------
__global__ void l1rev_kernel() {
    int idx = blockIdx.x * blockDim.x + threadIdx.x;
    if (idx >= 128 * 128) return;
    int b = idx >> 7, j = idx & 127;
    const float* xg = g_xg1r + b * 512;
    float iv = xg[j], gv = xg[256 + j], ov = xg[384 + j];
    float c = sigf(iv) * tanh_fast(gv);
    g_h1last[b * 256 + 128 + j] = sigf(ov) * tanh_fast(c);
}

// ---------------- final FC ----------------
__global__ void fc_kernel(const float* __restrict__ fcw, const float* __restrict__ fcb,
                          float* __restrict__ out) {
    int b = blockIdx.x;
    int lane = threadIdx.x;
    float v[8];
#pragma unroll
    for (int u = 0; u < 8; u++) v[u] = g_h1last[b * 256 + lane + u * 32];
    for (int c = 0; c < 10; c++) {
        float s = 0.f;
#pragma unroll
        for (int u = 0; u < 8; u++) s = fmaf(v[u], fcw[c * 256 + lane + u * 32], s);
#pragma unroll
        for (int o = 16; o; o >>= 1) s += __shfl_xor_sync(0xffffffffu, s, o);
        if (lane == 0) out[b * 10 + c] = s + fcb[c];
    }
}

// ---------------- launch ----------------
extern "C" void kernel_launch(void* const* d_in, const int* in_sizes, int n_in,
                              void* d_out, int out_size) {
    const int*   x        = (const int*)d_in[0];
    const float* emb      = (const float*)d_in[1];
    const float* wih_l0f  = (const float*)d_in[2];
    const float* whh_l0f  = (const float*)d_in[3];
    const float* bih_l0f  = (const float*)d_in[4];
    const float* bhh_l0f  = (const float*)d_in[5];
    const float* wih_l0r  = (const float*)d_in[6];
    const float* whh_l0r  = (const float*)d_in[7];
    const float* bih_l0r  = (const float*)d_in[8];
    const float* bhh_l0r  = (const float*)d_in[9];
    const float* wih_l1f  = (const float*)d_in[10];
    const float* whh_l1f  = (const float*)d_in[11];
    const float* bih_l1f  = (const float*)d_in[12];
    const float* bhh_l1f  = (const float*)d_in[13];
    const float* wih_l1r  = (const float*)d_in[14];
    const float* bih_l1r  = (const float*)d_in[16];
    const float* bhh_l1r  = (const float*)d_in[17];
    const float* fc_w     = (const float*)d_in[18];
    const float* fc_b     = (const float*)d_in[19];
    float* out = (float*)d_out;

    float *pX0, *pWpad, *pW1, *pB0, *pB1f, *pB1r, *pXg0, *pHs0, *pXg1f, *pXg1r, *pH1;
    cudaGetSymbolAddress((void**)&pX0,   g_X0);
    cudaGetSymbolAddress((void**)&pWpad, g_Wpad);
    cudaGetSymbolAddress((void**)&pW1,   g_W1);
    cudaGetSymbolAddress((void**)&pB0,   g_bias0);
    cudaGetSymbolAddress((void**)&pB1f,  g_bias1f);
    cudaGetSymbolAddress((void**)&pB1r,  g_bias1r);
    cudaGetSymbolAddress((void**)&pXg0,  g_xg0);
    cudaGetSymbolAddress((void**)&pHs0,  g_hs0);
    cudaGetSymbolAddress((void**)&pXg1f, g_xg1f);
    cudaGetSymbolAddress((void**)&pXg1r, g_xg1r);
    cudaGetSymbolAddress((void**)&pH1,   g_h1last);

    const int SMEM_SCAN = (MR * HP + MR * GP) * 4;   // 18816 B

    prep_kernel<<<128, 256>>>(wih_l0f, wih_l0r, wih_l1f,
                              bih_l0f, bhh_l0f, bih_l0r, bhh_l0r,
                              bih_l1f, bhh_l1f, bih_l1r, bhh_l1r);
    embed_kernel<<<2048, 256>>>(x, emb);

    // layer 0 input gates (tensor cores via mma.sync tf32): [65536,304] x [1024,304]^T
    {
        dim3 grid(1024 / 128, MTOT / 128);
        gemm_mma_kernel<<<grid, 256>>>(pX0, KPAD, pWpad, KPAD, pXg0, 1024, KPAD, pB0);
    }
    // layer 0 scan (both dirs): 32 CTAs (2 dirs x 16 chunks of 8 rows), MMA recurrence
    lstm_mma_kernel<2, true><<<32, 512, SMEM_SCAN>>>(pXg0, 1024, whh_l0f, whh_l0r, pHs0);

    // layer 1 forward input gates (tensor cores): [65536,256] x [512,256]^T
    {
        dim3 grid(512 / 128, MTOT / 128);
        gemm_mma_kernel<<<grid, 256>>>(pHs0, 256, pW1, 256, pXg1f, 512, 256, pB1f);
    }
    // layer 1 reverse: only t=T-1 row needed -> tiny GEMM (M=128), fp32 SIMT
    {
        dim3 grid(512 / 64, 1);
        gemm_bias_kernel<<<grid, 256>>>(pHs0 + 511 * 256, T_SEQ * 256, wih_l1r, 256,
                                        pXg1r, 512, 256, pB1r);
    }
    // layer 1 forward scan (only final h needed): 16 CTAs, MMA recurrence
    lstm_mma_kernel<1, false><<<16, 512, SMEM_SCAN>>>(pXg1f, 512, whh_l1f, whh_l1f, pH1);
    // layer 1 reverse: single step, elementwise
    l1rev_kernel<<<64, 256>>>();

    fc_kernel<<<128, 32>>>(fc_w, fc_b, out);
    (void)in_sizes; (void)n_in; (void)out_size;
}